// round 1
// baseline (speedup 1.0000x reference)
#include <cuda_runtime.h>
#include <math.h>

#define NN 50000
#define EE 800000
#define D  128

// Scratch (static __device__ globals: allocation-free per harness rules)
__device__ float g_P  [NN * D];
__device__ float g_agg[NN * D];
__device__ float g_h0 [NN * D];
__device__ float g_h1 [NN * D];

// ---------------------------------------------------------------------------
// C = act( A1@W1 [+ A2@W2] + bias ),  K = 128 fixed, N_out = 128 fixed.
// BM=64, BN=128, BK=32, 256 threads, per-thread micro-tile 4x8.
// act: 0 = relu, 1 = leaky_relu(0.01)
// ---------------------------------------------------------------------------
__global__ void gemm_act(const float* __restrict__ A1, const float* __restrict__ W1,
                         const float* __restrict__ A2, const float* __restrict__ W2,
                         const float* __restrict__ bias, float* __restrict__ C,
                         int N, int act)
{
    __shared__ float As[64][33];   // +1 pad: conflict-free column reads
    __shared__ float Bs[32][128];

    const int tid = threadIdx.x;
    const int tx  = tid & 15;      // 16 col groups * 8 cols = 128
    const int ty  = tid >> 4;      // 16 row groups * 4 rows = 64
    const int m0  = blockIdx.x * 64;

    float acc[4][8];
#pragma unroll
    for (int i = 0; i < 4; i++)
#pragma unroll
        for (int j = 0; j < 8; j++) acc[i][j] = 0.f;

    for (int s = 0; s < 2; s++) {
        const float* A = s ? A2 : A1;
        const float* W = s ? W2 : W1;
        if (A == nullptr) break;

        for (int k0 = 0; k0 < D; k0 += 32) {
            __syncthreads();  // previous chunk consumers done
            // A tile: 64x32 = 512 float4, 2 per thread
#pragma unroll
            for (int i = 0; i < 2; i++) {
                int idx = i * 256 + tid;
                int r   = idx >> 3;
                int c   = (idx & 7) << 2;
                float4 v = make_float4(0.f, 0.f, 0.f, 0.f);
                if (m0 + r < N)
                    v = *(const float4*)(A + (size_t)(m0 + r) * D + k0 + c);
                As[r][c] = v.x; As[r][c + 1] = v.y; As[r][c + 2] = v.z; As[r][c + 3] = v.w;
            }
            // W tile: 32x128 = 1024 float4, 4 per thread
#pragma unroll
            for (int i = 0; i < 4; i++) {
                int idx = i * 256 + tid;
                int r   = idx >> 5;
                int c   = (idx & 31) << 2;
                *(float4*)&Bs[r][c] = *(const float4*)(W + (size_t)(k0 + r) * D + c);
            }
            __syncthreads();

#pragma unroll
            for (int k = 0; k < 32; k++) {
                float a0 = As[ty * 4 + 0][k];
                float a1 = As[ty * 4 + 1][k];
                float a2 = As[ty * 4 + 2][k];
                float a3 = As[ty * 4 + 3][k];
                float4 b0 = *(float4*)&Bs[k][tx * 8];
                float4 b1 = *(float4*)&Bs[k][tx * 8 + 4];
                float bb[8] = {b0.x, b0.y, b0.z, b0.w, b1.x, b1.y, b1.z, b1.w};
#pragma unroll
                for (int j = 0; j < 8; j++) {
                    acc[0][j] = fmaf(a0, bb[j], acc[0][j]);
                    acc[1][j] = fmaf(a1, bb[j], acc[1][j]);
                    acc[2][j] = fmaf(a2, bb[j], acc[2][j]);
                    acc[3][j] = fmaf(a3, bb[j], acc[3][j]);
                }
            }
        }
    }

    float bcol[8];
#pragma unroll
    for (int j = 0; j < 8; j++) bcol[j] = bias ? bias[tx * 8 + j] : 0.f;

#pragma unroll
    for (int i = 0; i < 4; i++) {
        int r = m0 + ty * 4 + i;
        if (r >= N) continue;
#pragma unroll
        for (int j = 0; j < 8; j++) {
            float v = acc[i][j] + bcol[j];
            acc[i][j] = (act == 0) ? fmaxf(v, 0.f) : (v > 0.f ? v : 0.01f * v);
        }
        *(float4*)(C + (size_t)r * D + tx * 8) =
            make_float4(acc[i][0], acc[i][1], acc[i][2], acc[i][3]);
        *(float4*)(C + (size_t)r * D + tx * 8 + 4) =
            make_float4(acc[i][4], acc[i][5], acc[i][6], acc[i][7]);
    }
}

// ---------------------------------------------------------------------------
// Zero fill (float4)
// ---------------------------------------------------------------------------
__global__ void zero_kernel(float4* __restrict__ p, int n4)
{
    int i = blockIdx.x * blockDim.x + threadIdx.x;
    int stride = gridDim.x * blockDim.x;
    float4 z = make_float4(0.f, 0.f, 0.f, 0.f);
    for (; i < n4; i += stride) p[i] = z;
}

// ---------------------------------------------------------------------------
// Segment max: one warp per edge. agg must be zero-initialized.
// Values are >= 0 (post relu), so int atomicMax on float bits is exact,
// and v == 0 contributes nothing (init is 0) -> skip.
// ---------------------------------------------------------------------------
__global__ void edge_max(const float* __restrict__ P, const int* __restrict__ src,
                         const int* __restrict__ dst, int* __restrict__ agg, int E)
{
    int gt   = blockIdx.x * blockDim.x + threadIdx.x;
    int e    = gt >> 5;
    int lane = gt & 31;
    if (e >= E) return;
    int s = src[e];
    int d = dst[e];
    float4 v = *(const float4*)(P + (size_t)s * D + lane * 4);
    int* a = agg + (size_t)d * D + lane * 4;
    if (v.x > 0.f) atomicMax(a + 0, __float_as_int(v.x));
    if (v.y > 0.f) atomicMax(a + 1, __float_as_int(v.y));
    if (v.z > 0.f) atomicMax(a + 2, __float_as_int(v.z));
    if (v.w > 0.f) atomicMax(a + 3, __float_as_int(v.w));
}

// ---------------------------------------------------------------------------
// out = sigmoid(h @ Wout + bout), Wout: [128,10]. One warp per node.
// ---------------------------------------------------------------------------
__global__ void out_proj(const float* __restrict__ h, const float* __restrict__ Wout,
                         const float* __restrict__ bout, float* __restrict__ out, int N)
{
    __shared__ float Ws[D * 10];
    __shared__ float bs[10];
    for (int i = threadIdx.x; i < D * 10; i += blockDim.x) Ws[i] = Wout[i];
    if (threadIdx.x < 10) bs[threadIdx.x] = bout[threadIdx.x];
    __syncthreads();

    int gt   = blockIdx.x * blockDim.x + threadIdx.x;
    int node = gt >> 5;
    int lane = gt & 31;
    if (node >= N) return;

    float4 hv = *(const float4*)(h + (size_t)node * D + lane * 4);
#pragma unroll
    for (int c = 0; c < 10; c++) {
        float s = hv.x * Ws[(lane * 4 + 0) * 10 + c]
                + hv.y * Ws[(lane * 4 + 1) * 10 + c]
                + hv.z * Ws[(lane * 4 + 2) * 10 + c]
                + hv.w * Ws[(lane * 4 + 3) * 10 + c];
#pragma unroll
        for (int off = 16; off; off >>= 1) s += __shfl_xor_sync(0xFFFFFFFFu, s, off);
        if (lane == 0) out[(size_t)node * 10 + c] = 1.f / (1.f + expf(-(s + bs[c])));
    }
}

// ---------------------------------------------------------------------------
extern "C" void kernel_launch(void* const* d_in, const int* in_sizes, int n_in,
                              void* d_out, int out_size)
{
    const float* x   = (const float*)d_in[0];
    const int*   src = (const int*)d_in[1];
    const int*   dst = (const int*)d_in[2];
    const float* Wp[3] = {(const float*)d_in[3],  (const float*)d_in[8],  (const float*)d_in[13]};
    const float* bp[3] = {(const float*)d_in[4],  (const float*)d_in[9],  (const float*)d_in[14]};
    const float* Ws[3] = {(const float*)d_in[5],  (const float*)d_in[10], (const float*)d_in[15]};
    const float* Wn[3] = {(const float*)d_in[6],  (const float*)d_in[11], (const float*)d_in[16]};
    const float* bn[3] = {(const float*)d_in[7],  (const float*)d_in[12], (const float*)d_in[17]};
    const float* Wout  = (const float*)d_in[18];
    const float* bout  = (const float*)d_in[19];

    const int N = in_sizes[0] / D;
    const int E = in_sizes[1];

    float *P, *agg, *h0, *h1;
    cudaGetSymbolAddress((void**)&P,   g_P);
    cudaGetSymbolAddress((void**)&agg, g_agg);
    cudaGetSymbolAddress((void**)&h0,  g_h0);
    cudaGetSymbolAddress((void**)&h1,  g_h1);

    const int gemmBlocks = (N + 63) / 64;
    const int edgeBlocks = (E * 32 + 255) / 256;

    const float* h = x;
    float* hbuf[3] = {h0, h1, h0};

    for (int l = 0; l < 3; l++) {
        // P = relu(h @ Wpool + bpool)   (per-node; gather commutes with linear)
        gemm_act<<<gemmBlocks, 256>>>(h, Wp[l], nullptr, nullptr, bp[l], P, N, 0);
        // agg = max over incoming edges of P[src], clamped at 0
        zero_kernel<<<2048, 256>>>((float4*)agg, N * D / 4);
        edge_max<<<edgeBlocks, 256>>>(P, src, dst, (int*)agg, E);
        // h' = leaky_relu(h @ Wself + agg @ Wneigh + bneigh)
        gemm_act<<<gemmBlocks, 256>>>(h, Ws[l], agg, Wn[l], bn[l], hbuf[l], N, 1);
        h = hbuf[l];
    }

    out_proj<<<(N + 7) / 8, 256>>>(h, Wout, bout, (float*)d_out, N);
}

// round 4
// speedup vs baseline: 2.0324x; 2.0324x over previous
#include <cuda_runtime.h>
#include <cstdint>
#include <math.h>

#define NN 50000
#define EE 800000
#define D  128

// Scratch (static __device__ globals: allocation-free per harness rules)
__device__ float g_P  [NN * D];
__device__ float g_agg[NN * D];
__device__ float g_h0 [NN * D];
__device__ float g_h1 [NN * D];

__device__ __forceinline__ uint32_t tf32r(float x) {  // round-to-nearest tf32 bits
    uint32_t r;
    asm("cvt.rna.tf32.f32 %0, %1;" : "=r"(r) : "f"(x));
    return r;
}

__device__ __forceinline__ void mma_tf32(float* c, const uint32_t* a, uint32_t b0, uint32_t b1) {
    asm volatile(
        "mma.sync.aligned.m16n8k8.row.col.f32.tf32.tf32.f32 "
        "{%0,%1,%2,%3}, {%4,%5,%6,%7}, {%8,%9}, {%0,%1,%2,%3};"
        : "+f"(c[0]), "+f"(c[1]), "+f"(c[2]), "+f"(c[3])
        : "r"(a[0]), "r"(a[1]), "r"(a[2]), "r"(a[3]), "r"(b0), "r"(b1));
}

// ===========================================================================
// Tensor-core GEMM (mma.sync tf32):  C = act( A1@W1 [+ A2@W2] + bias ).
// M tile 128/CTA, N=K=128 full. 8 warps (4m x 2n), warp tile 32x64.
// A: [M,K] row-major; W: [K,N] row-major (natural layout == mma "col" B frag).
// SMEM rows padded to 132 floats -> conflict-free frag loads.
// act: 0 = relu, 1 = leaky_relu(0.01)
// ===========================================================================
#define LDP 132
static constexpr uint32_t GEMM_SMEM = (2 * 128 * LDP + 128) * 4;  // 135680 B

__global__ __launch_bounds__(256, 1)
void gemm_mma(const float* __restrict__ A1, const float* __restrict__ W1,
              const float* __restrict__ A2, const float* __restrict__ W2,
              const float* __restrict__ bias, float* __restrict__ C,
              int N, int act)
{
    extern __shared__ uint32_t sm[];
    uint32_t* As = sm;                       // [128][LDP]
    uint32_t* Bs = sm + 128 * LDP;           // [128][LDP]
    float*    bs = (float*)(sm + 2 * 128 * LDP);

    const int tid  = threadIdx.x;
    const int wid  = tid >> 5;
    const int lane = tid & 31;
    const int wm   = (wid & 3) * 32;         // warp row offset
    const int wn   = (wid >> 2) * 64;        // warp col offset
    const int lr   = lane >> 2;              // 0..7
    const int lc   = lane & 3;               // 0..3
    const int m0   = blockIdx.x * 128;

    if (tid < 128) bs[tid] = bias[tid];

    float acc[2][8][4];
    #pragma unroll
    for (int mi = 0; mi < 2; mi++)
        #pragma unroll
        for (int ni = 0; ni < 8; ni++)
            #pragma unroll
            for (int j = 0; j < 4; j++) acc[mi][ni][j] = 0.f;

    const int npass = (A2 != nullptr) ? 2 : 1;
    for (int p = 0; p < npass; p++) {
        const float* A = p ? A2 : A1;
        const float* W = p ? W2 : W1;

        if (p) __syncthreads();  // all warps done with pass-0 SMEM

        // A tile: 4096 float4, 16 per thread, cvt->tf32
        #pragma unroll
        for (int i = 0; i < 16; i++) {
            int i4 = i * 256 + tid;
            int r = i4 >> 5, c = (i4 & 31) << 2;
            float4 v = make_float4(0.f, 0.f, 0.f, 0.f);
            if (m0 + r < N) v = *(const float4*)(A + (size_t)(m0 + r) * D + c);
            *(uint4*)(As + r * LDP + c) = make_uint4(tf32r(v.x), tf32r(v.y), tf32r(v.z), tf32r(v.w));
        }
        // W tile (natural [k][n] layout)
        #pragma unroll
        for (int i = 0; i < 16; i++) {
            int i4 = i * 256 + tid;
            int r = i4 >> 5, c = (i4 & 31) << 2;
            float4 v = *(const float4*)(W + (size_t)r * D + c);
            *(uint4*)(Bs + r * LDP + c) = make_uint4(tf32r(v.x), tf32r(v.y), tf32r(v.z), tf32r(v.w));
        }
        __syncthreads();

        #pragma unroll
        for (int ks = 0; ks < 16; ks++) {
            const int k0 = ks * 8;
            uint32_t af[2][4];
            #pragma unroll
            for (int mi = 0; mi < 2; mi++) {
                int rb = wm + mi * 16 + lr;
                af[mi][0] = As[rb * LDP + k0 + lc];
                af[mi][1] = As[(rb + 8) * LDP + k0 + lc];
                af[mi][2] = As[rb * LDP + k0 + lc + 4];
                af[mi][3] = As[(rb + 8) * LDP + k0 + lc + 4];
            }
            #pragma unroll
            for (int ni = 0; ni < 8; ni++) {
                int cb = wn + ni * 8 + lr;
                uint32_t b0 = Bs[(k0 + lc) * LDP + cb];
                uint32_t b1 = Bs[(k0 + lc + 4) * LDP + cb];
                mma_tf32(acc[0][ni], af[0], b0, b1);
                mma_tf32(acc[1][ni], af[1], b0, b1);
            }
        }
    }

    // Epilogue: bias + activation + store (float2 per c-pair)
    #pragma unroll
    for (int mi = 0; mi < 2; mi++) {
        const int row0 = m0 + wm + mi * 16 + lr;
        #pragma unroll
        for (int ni = 0; ni < 8; ni++) {
            const int col = wn + ni * 8 + lc * 2;
            const float bb0 = bs[col], bb1 = bs[col + 1];
            float v0 = acc[mi][ni][0] + bb0;
            float v1 = acc[mi][ni][1] + bb1;
            float v2 = acc[mi][ni][2] + bb0;
            float v3 = acc[mi][ni][3] + bb1;
            if (act == 0) {
                v0 = fmaxf(v0, 0.f); v1 = fmaxf(v1, 0.f);
                v2 = fmaxf(v2, 0.f); v3 = fmaxf(v3, 0.f);
            } else {
                v0 = v0 > 0.f ? v0 : 0.01f * v0;  v1 = v1 > 0.f ? v1 : 0.01f * v1;
                v2 = v2 > 0.f ? v2 : 0.01f * v2;  v3 = v3 > 0.f ? v3 : 0.01f * v3;
            }
            if (row0 < N)
                *(float2*)(C + (size_t)row0 * D + col) = make_float2(v0, v1);
            if (row0 + 8 < N)
                *(float2*)(C + (size_t)(row0 + 8) * D + col) = make_float2(v2, v3);
        }
    }
}

// ---------------------------------------------------------------------------
// Zero fill (float4)
// ---------------------------------------------------------------------------
__global__ void zero_kernel(float4* __restrict__ p, int n4)
{
    int i = blockIdx.x * blockDim.x + threadIdx.x;
    int stride = gridDim.x * blockDim.x;
    float4 z = make_float4(0.f, 0.f, 0.f, 0.f);
    for (; i < n4; i += stride) p[i] = z;
}

// ---------------------------------------------------------------------------
// Segment max: one warp per edge. agg must be zero-initialized.
// Post-relu values >= 0: int atomicMax on float bits is exact. Pre-check the
// current agg (plain load) and only atomic when strictly larger — stale-small
// read -> redundant atomic (no-op), stale-large -> skip a no-op. Race-safe.
// ---------------------------------------------------------------------------
__global__ void edge_max(const float* __restrict__ P, const int* __restrict__ src,
                         const int* __restrict__ dst, int* __restrict__ agg, int E)
{
    int gt   = blockIdx.x * blockDim.x + threadIdx.x;
    int e    = gt >> 5;
    int lane = gt & 31;
    if (e >= E) return;
    int s = src[e];
    int d = dst[e];
    float4 v = *(const float4*)(P + (size_t)s * D + lane * 4);
    int* a = agg + (size_t)d * D + lane * 4;
    int4 cur = *(const int4*)a;
    if (v.x > __int_as_float(cur.x)) atomicMax(a + 0, __float_as_int(v.x));
    if (v.y > __int_as_float(cur.y)) atomicMax(a + 1, __float_as_int(v.y));
    if (v.z > __int_as_float(cur.z)) atomicMax(a + 2, __float_as_int(v.z));
    if (v.w > __int_as_float(cur.w)) atomicMax(a + 3, __float_as_int(v.w));
}

// ---------------------------------------------------------------------------
// out = sigmoid(h @ Wout + bout), Wout: [128,10]. One warp per node.
// ---------------------------------------------------------------------------
__global__ void out_proj(const float* __restrict__ h, const float* __restrict__ Wout,
                         const float* __restrict__ bout, float* __restrict__ out, int N)
{
    __shared__ float Ws[D * 10];
    __shared__ float bs[10];
    for (int i = threadIdx.x; i < D * 10; i += blockDim.x) Ws[i] = Wout[i];
    if (threadIdx.x < 10) bs[threadIdx.x] = bout[threadIdx.x];
    __syncthreads();

    int gt   = blockIdx.x * blockDim.x + threadIdx.x;
    int node = gt >> 5;
    int lane = gt & 31;
    if (node >= N) return;

    float4 hv = *(const float4*)(h + (size_t)node * D + lane * 4);
#pragma unroll
    for (int c = 0; c < 10; c++) {
        float s = hv.x * Ws[(lane * 4 + 0) * 10 + c]
                + hv.y * Ws[(lane * 4 + 1) * 10 + c]
                + hv.z * Ws[(lane * 4 + 2) * 10 + c]
                + hv.w * Ws[(lane * 4 + 3) * 10 + c];
#pragma unroll
        for (int off = 16; off; off >>= 1) s += __shfl_xor_sync(0xFFFFFFFFu, s, off);
        if (lane == 0) out[(size_t)node * 10 + c] = 1.f / (1.f + expf(-(s + bs[c])));
    }
}

// ---------------------------------------------------------------------------
extern "C" void kernel_launch(void* const* d_in, const int* in_sizes, int n_in,
                              void* d_out, int out_size)
{
    const float* x   = (const float*)d_in[0];
    const int*   src = (const int*)d_in[1];
    const int*   dst = (const int*)d_in[2];
    const float* Wp[3] = {(const float*)d_in[3],  (const float*)d_in[8],  (const float*)d_in[13]};
    const float* bp[3] = {(const float*)d_in[4],  (const float*)d_in[9],  (const float*)d_in[14]};
    const float* Ws[3] = {(const float*)d_in[5],  (const float*)d_in[10], (const float*)d_in[15]};
    const float* Wn[3] = {(const float*)d_in[6],  (const float*)d_in[11], (const float*)d_in[16]};
    const float* bn[3] = {(const float*)d_in[7],  (const float*)d_in[12], (const float*)d_in[17]};
    const float* Wout  = (const float*)d_in[18];
    const float* bout  = (const float*)d_in[19];

    const int N = in_sizes[0] / D;
    const int E = in_sizes[1];

    float *P, *agg, *h0, *h1;
    cudaGetSymbolAddress((void**)&P,   g_P);
    cudaGetSymbolAddress((void**)&agg, g_agg);
    cudaGetSymbolAddress((void**)&h0,  g_h0);
    cudaGetSymbolAddress((void**)&h1,  g_h1);

    cudaFuncSetAttribute(gemm_mma, cudaFuncAttributeMaxDynamicSharedMemorySize, GEMM_SMEM);

    const int gemmBlocks = (N + 127) / 128;
    const int edgeBlocks = (E * 32 + 255) / 256;

    const float* h = x;
    float* hbuf[3] = {h0, h1, h0};

    for (int l = 0; l < 3; l++) {
        // P = relu(h @ Wpool + bpool)   (per-node; gather commutes with linear)
        gemm_mma<<<gemmBlocks, 256, GEMM_SMEM>>>(h, Wp[l], nullptr, nullptr, bp[l], P, N, 0);
        // agg = max over incoming edges of P[src], clamped at 0
        zero_kernel<<<2048, 256>>>((float4*)agg, N * D / 4);
        edge_max<<<edgeBlocks, 256>>>(P, src, dst, (int*)agg, E);
        // h' = leaky_relu(h @ Wself + agg @ Wneigh + bneigh)
        gemm_mma<<<gemmBlocks, 256, GEMM_SMEM>>>(h, Ws[l], agg, Wn[l], bn[l], hbuf[l], N, 1);
        h = hbuf[l];
    }

    out_proj<<<(N + 7) / 8, 256>>>(h, Wout, bout, (float*)d_out, N);
}

// round 5
// speedup vs baseline: 2.9520x; 1.4525x over previous
#include <cuda_runtime.h>
#include <cstdint>
#include <math.h>

#define NN 50000
#define EE 800000
#define D  128

// Scratch (static __device__ globals: allocation-free per harness rules)
__device__ float g_P  [NN * D];
__device__ float g_agg[NN * D];
__device__ float g_h0 [NN * D];
__device__ float g_h1 [NN * D];
__device__ int   g_deg[NN];
__device__ int   g_off[NN + 1];
__device__ int   g_cur[NN];
__device__ int   g_csr[EE];

__device__ __forceinline__ uint32_t tf32r(float x) {  // round-to-nearest tf32 bits
    uint32_t r;
    asm("cvt.rna.tf32.f32 %0, %1;" : "=r"(r) : "f"(x));
    return r;
}

__device__ __forceinline__ void mma_tf32(float* c, const uint32_t* a, uint32_t b0, uint32_t b1) {
    asm volatile(
        "mma.sync.aligned.m16n8k8.row.col.f32.tf32.tf32.f32 "
        "{%0,%1,%2,%3}, {%4,%5,%6,%7}, {%8,%9}, {%0,%1,%2,%3};"
        : "+f"(c[0]), "+f"(c[1]), "+f"(c[2]), "+f"(c[3])
        : "r"(a[0]), "r"(a[1]), "r"(a[2]), "r"(a[3]), "r"(b0), "r"(b1));
}

// ===========================================================================
// Tensor-core GEMM (mma.sync tf32):  C = act( A1@W1 [+ A2@W2] + bias ).
// M tile 128/CTA, N=K=128 full. 8 warps (4m x 2n), warp tile 32x64.
// ===========================================================================
#define LDP 132
static constexpr uint32_t GEMM_SMEM = (2 * 128 * LDP + 128) * 4;  // 135680 B

__global__ __launch_bounds__(256, 1)
void gemm_mma(const float* __restrict__ A1, const float* __restrict__ W1,
              const float* __restrict__ A2, const float* __restrict__ W2,
              const float* __restrict__ bias, float* __restrict__ C,
              int N, int act)
{
    extern __shared__ uint32_t sm[];
    uint32_t* As = sm;                       // [128][LDP]
    uint32_t* Bs = sm + 128 * LDP;           // [128][LDP]
    float*    bs = (float*)(sm + 2 * 128 * LDP);

    const int tid  = threadIdx.x;
    const int wid  = tid >> 5;
    const int lane = tid & 31;
    const int wm   = (wid & 3) * 32;
    const int wn   = (wid >> 2) * 64;
    const int lr   = lane >> 2;
    const int lc   = lane & 3;
    const int m0   = blockIdx.x * 128;

    if (tid < 128) bs[tid] = bias[tid];

    float acc[2][8][4];
    #pragma unroll
    for (int mi = 0; mi < 2; mi++)
        #pragma unroll
        for (int ni = 0; ni < 8; ni++)
            #pragma unroll
            for (int j = 0; j < 4; j++) acc[mi][ni][j] = 0.f;

    const int npass = (A2 != nullptr) ? 2 : 1;
    for (int p = 0; p < npass; p++) {
        const float* A = p ? A2 : A1;
        const float* W = p ? W2 : W1;

        if (p) __syncthreads();

        #pragma unroll
        for (int i = 0; i < 16; i++) {
            int i4 = i * 256 + tid;
            int r = i4 >> 5, c = (i4 & 31) << 2;
            float4 v = make_float4(0.f, 0.f, 0.f, 0.f);
            if (m0 + r < N) v = *(const float4*)(A + (size_t)(m0 + r) * D + c);
            *(uint4*)(As + r * LDP + c) = make_uint4(tf32r(v.x), tf32r(v.y), tf32r(v.z), tf32r(v.w));
        }
        #pragma unroll
        for (int i = 0; i < 16; i++) {
            int i4 = i * 256 + tid;
            int r = i4 >> 5, c = (i4 & 31) << 2;
            float4 v = *(const float4*)(W + (size_t)r * D + c);
            *(uint4*)(Bs + r * LDP + c) = make_uint4(tf32r(v.x), tf32r(v.y), tf32r(v.z), tf32r(v.w));
        }
        __syncthreads();

        #pragma unroll
        for (int ks = 0; ks < 16; ks++) {
            const int k0 = ks * 8;
            uint32_t af[2][4];
            #pragma unroll
            for (int mi = 0; mi < 2; mi++) {
                int rb = wm + mi * 16 + lr;
                af[mi][0] = As[rb * LDP + k0 + lc];
                af[mi][1] = As[(rb + 8) * LDP + k0 + lc];
                af[mi][2] = As[rb * LDP + k0 + lc + 4];
                af[mi][3] = As[(rb + 8) * LDP + k0 + lc + 4];
            }
            #pragma unroll
            for (int ni = 0; ni < 8; ni++) {
                int cb = wn + ni * 8 + lr;
                uint32_t b0 = Bs[(k0 + lc) * LDP + cb];
                uint32_t b1 = Bs[(k0 + lc + 4) * LDP + cb];
                mma_tf32(acc[0][ni], af[0], b0, b1);
                mma_tf32(acc[1][ni], af[1], b0, b1);
            }
        }
    }

    #pragma unroll
    for (int mi = 0; mi < 2; mi++) {
        const int row0 = m0 + wm + mi * 16 + lr;
        #pragma unroll
        for (int ni = 0; ni < 8; ni++) {
            const int col = wn + ni * 8 + lc * 2;
            const float bb0 = bs[col], bb1 = bs[col + 1];
            float v0 = acc[mi][ni][0] + bb0;
            float v1 = acc[mi][ni][1] + bb1;
            float v2 = acc[mi][ni][2] + bb0;
            float v3 = acc[mi][ni][3] + bb1;
            if (act == 0) {
                v0 = fmaxf(v0, 0.f); v1 = fmaxf(v1, 0.f);
                v2 = fmaxf(v2, 0.f); v3 = fmaxf(v3, 0.f);
            } else {
                v0 = v0 > 0.f ? v0 : 0.01f * v0;  v1 = v1 > 0.f ? v1 : 0.01f * v1;
                v2 = v2 > 0.f ? v2 : 0.01f * v2;  v3 = v3 > 0.f ? v3 : 0.01f * v3;
            }
            if (row0 < N)
                *(float2*)(C + (size_t)row0 * D + col) = make_float2(v0, v1);
            if (row0 + 8 < N)
                *(float2*)(C + (size_t)(row0 + 8) * D + col) = make_float2(v2, v3);
        }
    }
}

// ===========================================================================
// CSR build (once per launch): deg histogram -> exclusive scan -> ticket fill.
// ===========================================================================
__global__ void zero_deg(int* __restrict__ deg, int n)
{
    int i = blockIdx.x * blockDim.x + threadIdx.x;
    if (i < n) deg[i] = 0;
}

__global__ void hist_deg(const int* __restrict__ dst, int* __restrict__ deg, int E)
{
    int i = blockIdx.x * blockDim.x + threadIdx.x;
    if (i < E) atomicAdd(&deg[dst[i]], 1);
}

// Single-block cooperative exclusive scan over NN elements.
__global__ void scan_deg(const int* __restrict__ deg, int* __restrict__ off,
                         int* __restrict__ cur, int n)
{
    __shared__ int sh[1024];
    __shared__ int carry_s;
    const int tid = threadIdx.x;
    if (tid == 0) carry_s = 0;
    __syncthreads();

    for (int base = 0; base < n; base += 1024) {
        int v = (base + tid < n) ? deg[base + tid] : 0;
        sh[tid] = v;
        __syncthreads();
        #pragma unroll
        for (int ofs = 1; ofs < 1024; ofs <<= 1) {
            int t = (tid >= ofs) ? sh[tid - ofs] : 0;
            __syncthreads();
            sh[tid] += t;
            __syncthreads();
        }
        int incl = sh[tid];
        int excl = incl - v + carry_s;
        if (base + tid < n) { off[base + tid] = excl; cur[base + tid] = excl; }
        __syncthreads();
        if (tid == 1023) carry_s += incl;   // block total
        __syncthreads();
    }
    if (tid == 0) off[n] = carry_s;
}

__global__ void fill_csr(const int* __restrict__ src, const int* __restrict__ dst,
                         int* __restrict__ cur, int* __restrict__ csr, int E)
{
    int i = blockIdx.x * blockDim.x + threadIdx.x;
    if (i < E) {
        int pos = atomicAdd(&cur[dst[i]], 1);
        csr[pos] = src[i];
    }
}

// ===========================================================================
// Gather-max over CSR: warp per node, lane owns 4 floats. No atomics.
// Empty segment -> zeros (== reference's clamp of -inf to 0).
// ===========================================================================
__device__ __forceinline__ float4 max4(float4 a, float4 b) {
    return make_float4(fmaxf(a.x, b.x), fmaxf(a.y, b.y), fmaxf(a.z, b.z), fmaxf(a.w, b.w));
}

__global__ __launch_bounds__(256)
void gather_max(const float* __restrict__ P, const int* __restrict__ off,
                const int* __restrict__ csr, float* __restrict__ agg, int N)
{
    int gt   = blockIdx.x * blockDim.x + threadIdx.x;
    int node = gt >> 5;
    int lane = gt & 31;
    if (node >= N) return;

    int e  = off[node];
    int e1 = off[node + 1];
    float4 m = make_float4(0.f, 0.f, 0.f, 0.f);

    for (; e + 3 < e1; e += 4) {   // 4-way MLP
        int s0 = csr[e], s1 = csr[e + 1], s2 = csr[e + 2], s3 = csr[e + 3];
        float4 v0 = *(const float4*)(P + (size_t)s0 * D + lane * 4);
        float4 v1 = *(const float4*)(P + (size_t)s1 * D + lane * 4);
        float4 v2 = *(const float4*)(P + (size_t)s2 * D + lane * 4);
        float4 v3 = *(const float4*)(P + (size_t)s3 * D + lane * 4);
        m = max4(m, max4(max4(v0, v1), max4(v2, v3)));
    }
    for (; e < e1; e++) {
        int s = csr[e];
        m = max4(m, *(const float4*)(P + (size_t)s * D + lane * 4));
    }
    *(float4*)(agg + (size_t)node * D + lane * 4) = m;
}

// ---------------------------------------------------------------------------
// out = sigmoid(h @ Wout + bout), Wout: [128,10]. One warp per node.
// ---------------------------------------------------------------------------
__global__ void out_proj(const float* __restrict__ h, const float* __restrict__ Wout,
                         const float* __restrict__ bout, float* __restrict__ out, int N)
{
    __shared__ float Ws[D * 10];
    __shared__ float bs[10];
    for (int i = threadIdx.x; i < D * 10; i += blockDim.x) Ws[i] = Wout[i];
    if (threadIdx.x < 10) bs[threadIdx.x] = bout[threadIdx.x];
    __syncthreads();

    int gt   = blockIdx.x * blockDim.x + threadIdx.x;
    int node = gt >> 5;
    int lane = gt & 31;
    if (node >= N) return;

    float4 hv = *(const float4*)(h + (size_t)node * D + lane * 4);
#pragma unroll
    for (int c = 0; c < 10; c++) {
        float s = hv.x * Ws[(lane * 4 + 0) * 10 + c]
                + hv.y * Ws[(lane * 4 + 1) * 10 + c]
                + hv.z * Ws[(lane * 4 + 2) * 10 + c]
                + hv.w * Ws[(lane * 4 + 3) * 10 + c];
#pragma unroll
        for (int off = 16; off; off >>= 1) s += __shfl_xor_sync(0xFFFFFFFFu, s, off);
        if (lane == 0) out[(size_t)node * 10 + c] = 1.f / (1.f + expf(-(s + bs[c])));
    }
}

// ---------------------------------------------------------------------------
extern "C" void kernel_launch(void* const* d_in, const int* in_sizes, int n_in,
                              void* d_out, int out_size)
{
    const float* x   = (const float*)d_in[0];
    const int*   src = (const int*)d_in[1];
    const int*   dst = (const int*)d_in[2];
    const float* Wp[3] = {(const float*)d_in[3],  (const float*)d_in[8],  (const float*)d_in[13]};
    const float* bp[3] = {(const float*)d_in[4],  (const float*)d_in[9],  (const float*)d_in[14]};
    const float* Ws[3] = {(const float*)d_in[5],  (const float*)d_in[10], (const float*)d_in[15]};
    const float* Wn[3] = {(const float*)d_in[6],  (const float*)d_in[11], (const float*)d_in[16]};
    const float* bn[3] = {(const float*)d_in[7],  (const float*)d_in[12], (const float*)d_in[17]};
    const float* Wout  = (const float*)d_in[18];
    const float* bout  = (const float*)d_in[19];

    const int N = in_sizes[0] / D;
    const int E = in_sizes[1];

    float *P, *agg, *h0, *h1;
    int *deg, *off, *cur, *csr;
    cudaGetSymbolAddress((void**)&P,   g_P);
    cudaGetSymbolAddress((void**)&agg, g_agg);
    cudaGetSymbolAddress((void**)&h0,  g_h0);
    cudaGetSymbolAddress((void**)&h1,  g_h1);
    cudaGetSymbolAddress((void**)&deg, g_deg);
    cudaGetSymbolAddress((void**)&off, g_off);
    cudaGetSymbolAddress((void**)&cur, g_cur);
    cudaGetSymbolAddress((void**)&csr, g_csr);

    cudaFuncSetAttribute(gemm_mma, cudaFuncAttributeMaxDynamicSharedMemorySize, GEMM_SMEM);

    // ---- CSR build (dst-grouped incoming edge lists) ----
    zero_deg<<<(N + 255) / 256, 256>>>(deg, N);
    hist_deg<<<(E + 255) / 256, 256>>>(dst, deg, E);
    scan_deg<<<1, 1024>>>(deg, off, cur, N);
    fill_csr<<<(E + 255) / 256, 256>>>(src, dst, cur, csr, E);

    const int gemmBlocks   = (N + 127) / 128;
    const int gatherBlocks = (N * 32 + 255) / 256;

    const float* h = x;
    float* hbuf[3] = {h0, h1, h0};

    for (int l = 0; l < 3; l++) {
        // P = relu(h @ Wpool + bpool)   (per-node; gather commutes with linear)
        gemm_mma<<<gemmBlocks, 256, GEMM_SMEM>>>(h, Wp[l], nullptr, nullptr, bp[l], P, N, 0);
        // agg = max over incoming edges of P[src], clamped at 0 (gather, no atomics)
        gather_max<<<gatherBlocks, 256>>>(P, off, csr, agg, N);
        // h' = leaky_relu(h @ Wself + agg @ Wneigh + bneigh)
        gemm_mma<<<gemmBlocks, 256, GEMM_SMEM>>>(h, Ws[l], agg, Wn[l], bn[l], hbuf[l], N, 1);
        h = hbuf[l];
    }

    out_proj<<<(N + 7) / 8, 256>>>(h, Wout, bout, (float*)d_out, N);
}

// round 6
// speedup vs baseline: 3.1479x; 1.0664x over previous
#include <cuda_runtime.h>
#include <cstdint>
#include <math.h>

#define NN 50000
#define EE 800000
#define D  128

// Scratch (static __device__ globals: allocation-free per harness rules)
__device__ float g_P  [NN * D];
__device__ float g_agg[NN * D];
__device__ float g_h0 [NN * D];
__device__ float g_h1 [NN * D];
__device__ int   g_deg[NN];
__device__ int   g_off[NN + 1];
__device__ int   g_cur[NN];
__device__ int   g_csr[EE];

__device__ __forceinline__ uint32_t tf32r(float x) {  // round-to-nearest tf32 bits
    uint32_t r;
    asm("cvt.rna.tf32.f32 %0, %1;" : "=r"(r) : "f"(x));
    return r;
}

__device__ __forceinline__ void mma_tf32(float* c, const uint32_t* a, uint32_t b0, uint32_t b1) {
    asm volatile(
        "mma.sync.aligned.m16n8k8.row.col.f32.tf32.tf32.f32 "
        "{%0,%1,%2,%3}, {%4,%5,%6,%7}, {%8,%9}, {%0,%1,%2,%3};"
        : "+f"(c[0]), "+f"(c[1]), "+f"(c[2]), "+f"(c[3])
        : "r"(a[0]), "r"(a[1]), "r"(a[2]), "r"(a[3]), "r"(b0), "r"(b1));
}

// ===========================================================================
// Tensor-core GEMM (mma.sync tf32):  C = act( A1@W1 [+ A2@W2] + bias ).
// M tile 128/CTA, N=K=128 full. 512 threads, 16 warps (4m x 4n),
// warp tile 32x32 -> 4 warps/SMSP to hide LDS->MMA latency.
// A: [M,K] row-major; W: [K,N] row-major (natural layout == mma "col" B frag).
// act: 0 = relu, 1 = leaky_relu(0.01)
// ===========================================================================
#define LDP 132
static constexpr uint32_t GEMM_SMEM = (2 * 128 * LDP + 128) * 4;  // 135680 B

__global__ __launch_bounds__(512, 1)
void gemm_mma(const float* __restrict__ A1, const float* __restrict__ W1,
              const float* __restrict__ A2, const float* __restrict__ W2,
              const float* __restrict__ bias, float* __restrict__ C,
              int N, int act)
{
    extern __shared__ uint32_t sm[];
    uint32_t* As = sm;                       // [128][LDP]
    uint32_t* Bs = sm + 128 * LDP;           // [128][LDP]
    float*    bs = (float*)(sm + 2 * 128 * LDP);

    const int tid  = threadIdx.x;
    const int wid  = tid >> 5;
    const int lane = tid & 31;
    const int wm   = (wid & 3) * 32;         // warp row offset (4 m-warps)
    const int wn   = (wid >> 2) * 32;        // warp col offset (4 n-warps)
    const int lr   = lane >> 2;              // 0..7
    const int lc   = lane & 3;               // 0..3
    const int m0   = blockIdx.x * 128;

    if (tid < 128) bs[tid] = bias[tid];

    float acc[2][4][4];
    #pragma unroll
    for (int mi = 0; mi < 2; mi++)
        #pragma unroll
        for (int ni = 0; ni < 4; ni++)
            #pragma unroll
            for (int j = 0; j < 4; j++) acc[mi][ni][j] = 0.f;

    const int npass = (A2 != nullptr) ? 2 : 1;
    for (int p = 0; p < npass; p++) {
        const float* A = p ? A2 : A1;
        const float* W = p ? W2 : W1;

        if (p) __syncthreads();

        // A tile: 4096 float4 over 512 threads
        #pragma unroll
        for (int i = 0; i < 8; i++) {
            int i4 = i * 512 + tid;
            int r = i4 >> 5, c = (i4 & 31) << 2;
            float4 v = make_float4(0.f, 0.f, 0.f, 0.f);
            if (m0 + r < N) v = *(const float4*)(A + (size_t)(m0 + r) * D + c);
            *(uint4*)(As + r * LDP + c) = make_uint4(tf32r(v.x), tf32r(v.y), tf32r(v.z), tf32r(v.w));
        }
        // W tile (natural [k][n] layout)
        #pragma unroll
        for (int i = 0; i < 8; i++) {
            int i4 = i * 512 + tid;
            int r = i4 >> 5, c = (i4 & 31) << 2;
            float4 v = *(const float4*)(W + (size_t)r * D + c);
            *(uint4*)(Bs + r * LDP + c) = make_uint4(tf32r(v.x), tf32r(v.y), tf32r(v.z), tf32r(v.w));
        }
        __syncthreads();

        #pragma unroll
        for (int ks = 0; ks < 16; ks++) {
            const int k0 = ks * 8;
            uint32_t af[2][4];
            #pragma unroll
            for (int mi = 0; mi < 2; mi++) {
                int rb = wm + mi * 16 + lr;
                af[mi][0] = As[rb * LDP + k0 + lc];
                af[mi][1] = As[(rb + 8) * LDP + k0 + lc];
                af[mi][2] = As[rb * LDP + k0 + lc + 4];
                af[mi][3] = As[(rb + 8) * LDP + k0 + lc + 4];
            }
            #pragma unroll
            for (int ni = 0; ni < 4; ni++) {
                int cb = wn + ni * 8 + lr;
                uint32_t b0 = Bs[(k0 + lc) * LDP + cb];
                uint32_t b1 = Bs[(k0 + lc + 4) * LDP + cb];
                mma_tf32(acc[0][ni], af[0], b0, b1);
                mma_tf32(acc[1][ni], af[1], b0, b1);
            }
        }
    }

    // Epilogue: bias + activation + store
    #pragma unroll
    for (int mi = 0; mi < 2; mi++) {
        const int row0 = m0 + wm + mi * 16 + lr;
        #pragma unroll
        for (int ni = 0; ni < 4; ni++) {
            const int col = wn + ni * 8 + lc * 2;
            const float bb0 = bs[col], bb1 = bs[col + 1];
            float v0 = acc[mi][ni][0] + bb0;
            float v1 = acc[mi][ni][1] + bb1;
            float v2 = acc[mi][ni][2] + bb0;
            float v3 = acc[mi][ni][3] + bb1;
            if (act == 0) {
                v0 = fmaxf(v0, 0.f); v1 = fmaxf(v1, 0.f);
                v2 = fmaxf(v2, 0.f); v3 = fmaxf(v3, 0.f);
            } else {
                v0 = v0 > 0.f ? v0 : 0.01f * v0;  v1 = v1 > 0.f ? v1 : 0.01f * v1;
                v2 = v2 > 0.f ? v2 : 0.01f * v2;  v3 = v3 > 0.f ? v3 : 0.01f * v3;
            }
            if (row0 < N)
                *(float2*)(C + (size_t)row0 * D + col) = make_float2(v0, v1);
            if (row0 + 8 < N)
                *(float2*)(C + (size_t)(row0 + 8) * D + col) = make_float2(v2, v3);
        }
    }
}

// ===========================================================================
// CSR build (once per launch): deg histogram -> exclusive scan -> ticket fill.
// ===========================================================================
__global__ void zero_deg(int* __restrict__ deg, int n)
{
    int i = blockIdx.x * blockDim.x + threadIdx.x;
    if (i < n) deg[i] = 0;
}

__global__ void hist_deg(const int* __restrict__ dst, int* __restrict__ deg, int E)
{
    int i = blockIdx.x * blockDim.x + threadIdx.x;
    if (i < E) atomicAdd(&deg[dst[i]], 1);
}

// Single-block cooperative exclusive scan, shuffle-based (1024 threads).
__global__ void scan_deg(const int* __restrict__ deg, int* __restrict__ off,
                         int* __restrict__ cur, int n)
{
    __shared__ int wsum[32];
    __shared__ int carry_s;
    const int tid  = threadIdx.x;
    const int lane = tid & 31;
    const int w    = tid >> 5;
    if (tid == 0) carry_s = 0;
    __syncthreads();

    for (int base = 0; base < n; base += 1024) {
        int v = (base + tid < n) ? deg[base + tid] : 0;
        int x = v;
        #pragma unroll
        for (int o = 1; o < 32; o <<= 1) {
            int t = __shfl_up_sync(0xFFFFFFFFu, x, o);
            if (lane >= o) x += t;
        }
        if (lane == 31) wsum[w] = x;
        __syncthreads();
        if (w == 0) {
            int s = wsum[lane];
            #pragma unroll
            for (int o = 1; o < 32; o <<= 1) {
                int t = __shfl_up_sync(0xFFFFFFFFu, s, o);
                if (lane >= o) s += t;
            }
            wsum[lane] = s;
        }
        __syncthreads();
        int incl = x + (w ? wsum[w - 1] : 0);
        int excl = incl - v + carry_s;
        if (base + tid < n) { off[base + tid] = excl; cur[base + tid] = excl; }
        int total = wsum[31];
        __syncthreads();                       // all reads of carry_s/wsum done
        if (tid == 0) carry_s += total;
        __syncthreads();
    }
    if (tid == 0) off[n] = carry_s;
}

__global__ void fill_csr(const int* __restrict__ src, const int* __restrict__ dst,
                         int* __restrict__ cur, int* __restrict__ csr, int E)
{
    int i = blockIdx.x * blockDim.x + threadIdx.x;
    if (i < E) {
        int pos = atomicAdd(&cur[dst[i]], 1);
        csr[pos] = src[i];
    }
}

// ===========================================================================
// Gather-max over CSR: warp per node, lane owns 4 floats. No atomics.
// Empty segment -> zeros (== reference's clamp of -inf to 0).
// ===========================================================================
__device__ __forceinline__ float4 max4(float4 a, float4 b) {
    return make_float4(fmaxf(a.x, b.x), fmaxf(a.y, b.y), fmaxf(a.z, b.z), fmaxf(a.w, b.w));
}

__global__ __launch_bounds__(256)
void gather_max(const float* __restrict__ P, const int* __restrict__ off,
                const int* __restrict__ csr, float* __restrict__ agg, int N)
{
    int gt   = blockIdx.x * blockDim.x + threadIdx.x;
    int node = gt >> 5;
    int lane = gt & 31;
    if (node >= N) return;

    int e  = off[node];
    int e1 = off[node + 1];
    float4 m = make_float4(0.f, 0.f, 0.f, 0.f);

    for (; e + 3 < e1; e += 4) {   // 4-way MLP
        int s0 = csr[e], s1 = csr[e + 1], s2 = csr[e + 2], s3 = csr[e + 3];
        float4 v0 = *(const float4*)(P + (size_t)s0 * D + lane * 4);
        float4 v1 = *(const float4*)(P + (size_t)s1 * D + lane * 4);
        float4 v2 = *(const float4*)(P + (size_t)s2 * D + lane * 4);
        float4 v3 = *(const float4*)(P + (size_t)s3 * D + lane * 4);
        m = max4(m, max4(max4(v0, v1), max4(v2, v3)));
    }
    for (; e < e1; e++) {
        int s = csr[e];
        m = max4(m, *(const float4*)(P + (size_t)s * D + lane * 4));
    }
    *(float4*)(agg + (size_t)node * D + lane * 4) = m;
}

// ---------------------------------------------------------------------------
// out = sigmoid(h @ Wout + bout), Wout: [128,10]. One warp per node.
// ---------------------------------------------------------------------------
__global__ void out_proj(const float* __restrict__ h, const float* __restrict__ Wout,
                         const float* __restrict__ bout, float* __restrict__ out, int N)
{
    __shared__ float Ws[D * 10];
    __shared__ float bs[10];
    for (int i = threadIdx.x; i < D * 10; i += blockDim.x) Ws[i] = Wout[i];
    if (threadIdx.x < 10) bs[threadIdx.x] = bout[threadIdx.x];
    __syncthreads();

    int gt   = blockIdx.x * blockDim.x + threadIdx.x;
    int node = gt >> 5;
    int lane = gt & 31;
    if (node >= N) return;

    float4 hv = *(const float4*)(h + (size_t)node * D + lane * 4);
#pragma unroll
    for (int c = 0; c < 10; c++) {
        float s = hv.x * Ws[(lane * 4 + 0) * 10 + c]
                + hv.y * Ws[(lane * 4 + 1) * 10 + c]
                + hv.z * Ws[(lane * 4 + 2) * 10 + c]
                + hv.w * Ws[(lane * 4 + 3) * 10 + c];
#pragma unroll
        for (int off = 16; off; off >>= 1) s += __shfl_xor_sync(0xFFFFFFFFu, s, off);
        if (lane == 0) out[(size_t)node * 10 + c] = 1.f / (1.f + expf(-(s + bs[c])));
    }
}

// ---------------------------------------------------------------------------
extern "C" void kernel_launch(void* const* d_in, const int* in_sizes, int n_in,
                              void* d_out, int out_size)
{
    const float* x   = (const float*)d_in[0];
    const int*   src = (const int*)d_in[1];
    const int*   dst = (const int*)d_in[2];
    const float* Wp[3] = {(const float*)d_in[3],  (const float*)d_in[8],  (const float*)d_in[13]};
    const float* bp[3] = {(const float*)d_in[4],  (const float*)d_in[9],  (const float*)d_in[14]};
    const float* Ws[3] = {(const float*)d_in[5],  (const float*)d_in[10], (const float*)d_in[15]};
    const float* Wn[3] = {(const float*)d_in[6],  (const float*)d_in[11], (const float*)d_in[16]};
    const float* bn[3] = {(const float*)d_in[7],  (const float*)d_in[12], (const float*)d_in[17]};
    const float* Wout  = (const float*)d_in[18];
    const float* bout  = (const float*)d_in[19];

    const int N = in_sizes[0] / D;
    const int E = in_sizes[1];

    float *P, *agg, *h0, *h1;
    int *deg, *off, *cur, *csr;
    cudaGetSymbolAddress((void**)&P,   g_P);
    cudaGetSymbolAddress((void**)&agg, g_agg);
    cudaGetSymbolAddress((void**)&h0,  g_h0);
    cudaGetSymbolAddress((void**)&h1,  g_h1);
    cudaGetSymbolAddress((void**)&deg, g_deg);
    cudaGetSymbolAddress((void**)&off, g_off);
    cudaGetSymbolAddress((void**)&cur, g_cur);
    cudaGetSymbolAddress((void**)&csr, g_csr);

    cudaFuncSetAttribute(gemm_mma, cudaFuncAttributeMaxDynamicSharedMemorySize, GEMM_SMEM);

    // ---- CSR build (dst-grouped incoming edge lists) ----
    zero_deg<<<(N + 255) / 256, 256>>>(deg, N);
    hist_deg<<<(E + 255) / 256, 256>>>(dst, deg, E);
    scan_deg<<<1, 1024>>>(deg, off, cur, N);
    fill_csr<<<(E + 255) / 256, 256>>>(src, dst, cur, csr, E);

    const int gemmBlocks   = (N + 127) / 128;
    const int gatherBlocks = (N * 32 + 255) / 256;

    const float* h = x;
    float* hbuf[3] = {h0, h1, h0};

    for (int l = 0; l < 3; l++) {
        // P = relu(h @ Wpool + bpool)   (per-node; gather commutes with linear)
        gemm_mma<<<gemmBlocks, 512, GEMM_SMEM>>>(h, Wp[l], nullptr, nullptr, bp[l], P, N, 0);
        // agg = max over incoming edges of P[src], clamped at 0 (gather, no atomics)
        gather_max<<<gatherBlocks, 256>>>(P, off, csr, agg, N);
        // h' = leaky_relu(h @ Wself + agg @ Wneigh + bneigh)
        gemm_mma<<<gemmBlocks, 512, GEMM_SMEM>>>(h, Ws[l], agg, Wn[l], bn[l], hbuf[l], N, 1);
        h = hbuf[l];
    }

    out_proj<<<(N + 7) / 8, 256>>>(h, Wout, bout, (float*)d_out, N);
}

// round 8
// speedup vs baseline: 3.3470x; 1.0632x over previous
#include <cuda_runtime.h>
#include <cuda_fp16.h>
#include <cstdint>
#include <math.h>

#define NN 50000
#define EE 800000
#define D  128

// Scratch (static __device__ globals: allocation-free per harness rules)
__device__ __half g_P  [NN * D];     // pool output, fp16 (halves gather traffic)
__device__ float  g_agg[NN * D];
__device__ float  g_h0 [NN * D];
__device__ float  g_h1 [NN * D];
__device__ int    g_deg[NN];
__device__ int    g_off[NN + 1];
__device__ int    g_cur[NN];
__device__ int    g_csr[EE];

__device__ __forceinline__ uint32_t tf32r(float x) {  // round-to-nearest tf32 bits
    uint32_t r;
    asm("cvt.rna.tf32.f32 %0, %1;" : "=r"(r) : "f"(x));
    return r;
}

__device__ __forceinline__ void mma_tf32(float* c, const uint32_t* a, uint32_t b0, uint32_t b1) {
    asm volatile(
        "mma.sync.aligned.m16n8k8.row.col.f32.tf32.tf32.f32 "
        "{%0,%1,%2,%3}, {%4,%5,%6,%7}, {%8,%9}, {%0,%1,%2,%3};"
        : "+f"(c[0]), "+f"(c[1]), "+f"(c[2]), "+f"(c[3])
        : "r"(a[0]), "r"(a[1]), "r"(a[2]), "r"(a[3]), "r"(b0), "r"(b1));
}

// ===========================================================================
// Tensor-core GEMM (mma.sync tf32):  C = act( A1@W1 [+ A2@W2] + bias ).
// M tile 128/CTA, N=K=128 full. 512 threads, 16 warps (4m x 4n), warp 32x32.
// half_out: store fp16 (pool path) instead of fp32.
// act: 0 = relu, 1 = leaky_relu(0.01)
// ===========================================================================
#define LDP 132
static constexpr uint32_t GEMM_SMEM = (2 * 128 * LDP + 128) * 4;  // 135680 B

__global__ __launch_bounds__(512, 1)
void gemm_mma(const float* __restrict__ A1, const float* __restrict__ W1,
              const float* __restrict__ A2, const float* __restrict__ W2,
              const float* __restrict__ bias, void* __restrict__ Cout,
              int N, int act, int half_out)
{
    extern __shared__ uint32_t sm[];
    uint32_t* As = sm;                       // [128][LDP]
    uint32_t* Bs = sm + 128 * LDP;           // [128][LDP]
    float*    bs = (float*)(sm + 2 * 128 * LDP);

    const int tid  = threadIdx.x;
    const int wid  = tid >> 5;
    const int lane = tid & 31;
    const int wm   = (wid & 3) * 32;
    const int wn   = (wid >> 2) * 32;
    const int lr   = lane >> 2;
    const int lc   = lane & 3;
    const int m0   = blockIdx.x * 128;

    if (tid < 128) bs[tid] = bias[tid];

    float acc[2][4][4];
    #pragma unroll
    for (int mi = 0; mi < 2; mi++)
        #pragma unroll
        for (int ni = 0; ni < 4; ni++)
            #pragma unroll
            for (int j = 0; j < 4; j++) acc[mi][ni][j] = 0.f;

    const int npass = (A2 != nullptr) ? 2 : 1;
    for (int p = 0; p < npass; p++) {
        const float* A = p ? A2 : A1;
        const float* W = p ? W2 : W1;

        if (p) __syncthreads();

        #pragma unroll
        for (int i = 0; i < 8; i++) {
            int i4 = i * 512 + tid;
            int r = i4 >> 5, c = (i4 & 31) << 2;
            float4 v = make_float4(0.f, 0.f, 0.f, 0.f);
            if (m0 + r < N) v = *(const float4*)(A + (size_t)(m0 + r) * D + c);
            *(uint4*)(As + r * LDP + c) = make_uint4(tf32r(v.x), tf32r(v.y), tf32r(v.z), tf32r(v.w));
        }
        #pragma unroll
        for (int i = 0; i < 8; i++) {
            int i4 = i * 512 + tid;
            int r = i4 >> 5, c = (i4 & 31) << 2;
            float4 v = *(const float4*)(W + (size_t)r * D + c);
            *(uint4*)(Bs + r * LDP + c) = make_uint4(tf32r(v.x), tf32r(v.y), tf32r(v.z), tf32r(v.w));
        }
        __syncthreads();

        #pragma unroll
        for (int ks = 0; ks < 16; ks++) {
            const int k0 = ks * 8;
            uint32_t af[2][4];
            #pragma unroll
            for (int mi = 0; mi < 2; mi++) {
                int rb = wm + mi * 16 + lr;
                af[mi][0] = As[rb * LDP + k0 + lc];
                af[mi][1] = As[(rb + 8) * LDP + k0 + lc];
                af[mi][2] = As[rb * LDP + k0 + lc + 4];
                af[mi][3] = As[(rb + 8) * LDP + k0 + lc + 4];
            }
            #pragma unroll
            for (int ni = 0; ni < 4; ni++) {
                int cb = wn + ni * 8 + lr;
                uint32_t b0 = Bs[(k0 + lc) * LDP + cb];
                uint32_t b1 = Bs[(k0 + lc + 4) * LDP + cb];
                mma_tf32(acc[0][ni], af[0], b0, b1);
                mma_tf32(acc[1][ni], af[1], b0, b1);
            }
        }
    }

    // Epilogue: bias + activation + store (fp32 or fp16)
    #pragma unroll
    for (int mi = 0; mi < 2; mi++) {
        const int row0 = m0 + wm + mi * 16 + lr;
        #pragma unroll
        for (int ni = 0; ni < 4; ni++) {
            const int col = wn + ni * 8 + lc * 2;
            const float bb0 = bs[col], bb1 = bs[col + 1];
            float v0 = acc[mi][ni][0] + bb0;
            float v1 = acc[mi][ni][1] + bb1;
            float v2 = acc[mi][ni][2] + bb0;
            float v3 = acc[mi][ni][3] + bb1;
            if (act == 0) {
                v0 = fmaxf(v0, 0.f); v1 = fmaxf(v1, 0.f);
                v2 = fmaxf(v2, 0.f); v3 = fmaxf(v3, 0.f);
            } else {
                v0 = v0 > 0.f ? v0 : 0.01f * v0;  v1 = v1 > 0.f ? v1 : 0.01f * v1;
                v2 = v2 > 0.f ? v2 : 0.01f * v2;  v3 = v3 > 0.f ? v3 : 0.01f * v3;
            }
            if (half_out) {
                __half* C = (__half*)Cout;
                if (row0 < N)
                    *(__half2*)(C + (size_t)row0 * D + col) = __floats2half2_rn(v0, v1);
                if (row0 + 8 < N)
                    *(__half2*)(C + (size_t)(row0 + 8) * D + col) = __floats2half2_rn(v2, v3);
            } else {
                float* C = (float*)Cout;
                if (row0 < N)
                    *(float2*)(C + (size_t)row0 * D + col) = make_float2(v0, v1);
                if (row0 + 8 < N)
                    *(float2*)(C + (size_t)(row0 + 8) * D + col) = make_float2(v2, v3);
            }
        }
    }
}

// ===========================================================================
// CSR build (once per launch): deg histogram -> exclusive scan -> ticket fill.
// ===========================================================================
__global__ void zero_deg(int* __restrict__ deg, int n)
{
    int i = blockIdx.x * blockDim.x + threadIdx.x;
    if (i < n) deg[i] = 0;
}

__global__ void hist_deg(const int* __restrict__ dst, int* __restrict__ deg, int E)
{
    int i = blockIdx.x * blockDim.x + threadIdx.x;
    if (i < E) atomicAdd(&deg[dst[i]], 1);
}

// Single-block cooperative exclusive scan, shuffle-based (1024 threads).
__global__ void scan_deg(const int* __restrict__ deg, int* __restrict__ off,
                         int* __restrict__ cur, int n)
{
    __shared__ int wsum[32];
    __shared__ int carry_s;
    const int tid  = threadIdx.x;
    const int lane = tid & 31;
    const int w    = tid >> 5;
    if (tid == 0) carry_s = 0;
    __syncthreads();

    for (int base = 0; base < n; base += 1024) {
        int v = (base + tid < n) ? deg[base + tid] : 0;
        int x = v;
        #pragma unroll
        for (int o = 1; o < 32; o <<= 1) {
            int t = __shfl_up_sync(0xFFFFFFFFu, x, o);
            if (lane >= o) x += t;
        }
        if (lane == 31) wsum[w] = x;
        __syncthreads();
        if (w == 0) {
            int s = wsum[lane];
            #pragma unroll
            for (int o = 1; o < 32; o <<= 1) {
                int t = __shfl_up_sync(0xFFFFFFFFu, s, o);
                if (lane >= o) s += t;
            }
            wsum[lane] = s;
        }
        __syncthreads();
        int incl = x + (w ? wsum[w - 1] : 0);
        int excl = incl - v + carry_s;
        if (base + tid < n) { off[base + tid] = excl; cur[base + tid] = excl; }
        int total = wsum[31];
        __syncthreads();
        if (tid == 0) carry_s += total;
        __syncthreads();
    }
    if (tid == 0) off[n] = carry_s;
}

__global__ void fill_csr(const int* __restrict__ src, const int* __restrict__ dst,
                         int* __restrict__ cur, int* __restrict__ csr, int E)
{
    int i = blockIdx.x * blockDim.x + threadIdx.x;
    if (i < E) {
        int pos = atomicAdd(&cur[dst[i]], 1);
        csr[pos] = src[i];
    }
}

// ===========================================================================
// Gather-max over CSR (fp16 P): warp per node, lane owns 4 halves (8B).
// __hmax2 comparisons are exact; empty segment -> zeros (== reference clamp).
// Output agg as fp32 for the GEMM A path.
// ===========================================================================
__global__ __launch_bounds__(256)
void gather_max(const __half* __restrict__ P, const int* __restrict__ off,
                const int* __restrict__ csr, float* __restrict__ agg, int N)
{
    int gt   = blockIdx.x * blockDim.x + threadIdx.x;
    int node = gt >> 5;
    int lane = gt & 31;
    if (node >= N) return;

    int e  = off[node];
    int e1 = off[node + 1];
    __half2 m0 = __half2half2(__float2half(0.f));
    __half2 m1 = m0;

    for (; e + 3 < e1; e += 4) {   // 4-way MLP
        int s0 = csr[e], s1 = csr[e + 1], s2 = csr[e + 2], s3 = csr[e + 3];
        uint2 u0 = *(const uint2*)(P + (size_t)s0 * D + lane * 4);
        uint2 u1 = *(const uint2*)(P + (size_t)s1 * D + lane * 4);
        uint2 u2 = *(const uint2*)(P + (size_t)s2 * D + lane * 4);
        uint2 u3 = *(const uint2*)(P + (size_t)s3 * D + lane * 4);
        m0 = __hmax2(m0, __hmax2(__hmax2(*(__half2*)&u0.x, *(__half2*)&u1.x),
                                 __hmax2(*(__half2*)&u2.x, *(__half2*)&u3.x)));
        m1 = __hmax2(m1, __hmax2(__hmax2(*(__half2*)&u0.y, *(__half2*)&u1.y),
                                 __hmax2(*(__half2*)&u2.y, *(__half2*)&u3.y)));
    }
    for (; e < e1; e++) {
        int s = csr[e];
        uint2 u = *(const uint2*)(P + (size_t)s * D + lane * 4);
        m0 = __hmax2(m0, *(__half2*)&u.x);
        m1 = __hmax2(m1, *(__half2*)&u.y);
    }
    float2 f0 = __half22float2(m0);
    float2 f1 = __half22float2(m1);
    *(float4*)(agg + (size_t)node * D + lane * 4) = make_float4(f0.x, f0.y, f1.x, f1.y);
}

// ---------------------------------------------------------------------------
// out = sigmoid(h @ Wout + bout), Wout: [128,10]. One warp per node.
// ---------------------------------------------------------------------------
__global__ void out_proj(const float* __restrict__ h, const float* __restrict__ Wout,
                         const float* __restrict__ bout, float* __restrict__ out, int N)
{
    __shared__ float Ws[D * 10];
    __shared__ float bs[10];
    for (int i = threadIdx.x; i < D * 10; i += blockDim.x) Ws[i] = Wout[i];
    if (threadIdx.x < 10) bs[threadIdx.x] = bout[threadIdx.x];
    __syncthreads();

    int gt   = blockIdx.x * blockDim.x + threadIdx.x;
    int node = gt >> 5;
    int lane = gt & 31;
    if (node >= N) return;

    float4 hv = *(const float4*)(h + (size_t)node * D + lane * 4);
#pragma unroll
    for (int c = 0; c < 10; c++) {
        float s = hv.x * Ws[(lane * 4 + 0) * 10 + c]
                + hv.y * Ws[(lane * 4 + 1) * 10 + c]
                + hv.z * Ws[(lane * 4 + 2) * 10 + c]
                + hv.w * Ws[(lane * 4 + 3) * 10 + c];
#pragma unroll
        for (int off = 16; off; off >>= 1) s += __shfl_xor_sync(0xFFFFFFFFu, s, off);
        if (lane == 0) out[(size_t)node * 10 + c] = 1.f / (1.f + expf(-(s + bs[c])));
    }
}

// ---------------------------------------------------------------------------
extern "C" void kernel_launch(void* const* d_in, const int* in_sizes, int n_in,
                              void* d_out, int out_size)
{
    const float* x   = (const float*)d_in[0];
    const int*   src = (const int*)d_in[1];
    const int*   dst = (const int*)d_in[2];
    const float* Wp[3] = {(const float*)d_in[3],  (const float*)d_in[8],  (const float*)d_in[13]};
    const float* bp[3] = {(const float*)d_in[4],  (const float*)d_in[9],  (const float*)d_in[14]};
    const float* Ws[3] = {(const float*)d_in[5],  (const float*)d_in[10], (const float*)d_in[15]};
    const float* Wn[3] = {(const float*)d_in[6],  (const float*)d_in[11], (const float*)d_in[16]};
    const float* bn[3] = {(const float*)d_in[7],  (const float*)d_in[12], (const float*)d_in[17]};
    const float* Wout  = (const float*)d_in[18];
    const float* bout  = (const float*)d_in[19];

    const int N = in_sizes[0] / D;
    const int E = in_sizes[1];

    __half* P;
    float *agg, *h0, *h1;
    int *deg, *off, *cur, *csr;
    cudaGetSymbolAddress((void**)&P,   g_P);
    cudaGetSymbolAddress((void**)&agg, g_agg);
    cudaGetSymbolAddress((void**)&h0,  g_h0);
    cudaGetSymbolAddress((void**)&h1,  g_h1);
    cudaGetSymbolAddress((void**)&deg, g_deg);
    cudaGetSymbolAddress((void**)&off, g_off);
    cudaGetSymbolAddress((void**)&cur, g_cur);
    cudaGetSymbolAddress((void**)&csr, g_csr);

    cudaFuncSetAttribute(gemm_mma, cudaFuncAttributeMaxDynamicSharedMemorySize, GEMM_SMEM);

    // ---- CSR build (dst-grouped incoming edge lists) ----
    zero_deg<<<(N + 255) / 256, 256>>>(deg, N);
    hist_deg<<<(E + 255) / 256, 256>>>(dst, deg, E);
    scan_deg<<<1, 1024>>>(deg, off, cur, N);
    fill_csr<<<(E + 255) / 256, 256>>>(src, dst, cur, csr, E);

    const int gemmBlocks   = (N + 127) / 128;
    const int gatherBlocks = (N * 32 + 255) / 256;

    const float* h = x;
    float* hbuf[3] = {h0, h1, h0};

    for (int l = 0; l < 3; l++) {
        // P = relu(h @ Wpool + bpool), fp16   (gather commutes with linear)
        gemm_mma<<<gemmBlocks, 512, GEMM_SMEM>>>(h, Wp[l], nullptr, nullptr, bp[l], P, N, 0, 1);
        // agg = max over incoming edges of P[src], clamped at 0 (gather, no atomics)
        gather_max<<<gatherBlocks, 256>>>(P, off, csr, agg, N);
        // h' = leaky_relu(h @ Wself + agg @ Wneigh + bneigh)
        gemm_mma<<<gemmBlocks, 512, GEMM_SMEM>>>(h, Ws[l], agg, Wn[l], bn[l], hbuf[l], N, 1, 0);
        h = hbuf[l];
    }

    out_proj<<<(N + 7) / 8, 256>>>(h, Wout, bout, (float*)d_out, N);
}

// round 9
// speedup vs baseline: 3.3552x; 1.0025x over previous
#include <cuda_runtime.h>
#include <cuda_fp16.h>
#include <cstdint>
#include <math.h>

#define NN 50000
#define EE 800000
#define D  128

// Scratch (static __device__ globals: allocation-free per harness rules)
__device__ __half g_P  [NN * D];     // pool output, fp16 (halves gather traffic)
__device__ float  g_agg[NN * D];
__device__ float  g_h0 [NN * D];
__device__ float  g_h1 [NN * D];
__device__ int    g_deg[NN];
__device__ int    g_off[NN + 1];
__device__ int    g_cur[NN];
__device__ int    g_csr[EE];

__device__ __forceinline__ uint32_t tf32r(float x) {  // round-to-nearest tf32 bits
    uint32_t r;
    asm("cvt.rna.tf32.f32 %0, %1;" : "=r"(r) : "f"(x));
    return r;
}

__device__ __forceinline__ void mma_tf32(float* c, const uint32_t* a, uint32_t b0, uint32_t b1) {
    asm volatile(
        "mma.sync.aligned.m16n8k8.row.col.f32.tf32.tf32.f32 "
        "{%0,%1,%2,%3}, {%4,%5,%6,%7}, {%8,%9}, {%0,%1,%2,%3};"
        : "+f"(c[0]), "+f"(c[1]), "+f"(c[2]), "+f"(c[3])
        : "r"(a[0]), "r"(a[1]), "r"(a[2]), "r"(a[3]), "r"(b0), "r"(b1));
}

// ===========================================================================
// Tensor-core GEMM (mma.sync tf32):  C = act( A1@W1 [+ A2@W2] + bias ).
// M tile 128/CTA, N=K=128 full. 512 threads, 16 warps (4m x 4n), warp 32x32.
// half_out: store fp16 (pool path) instead of fp32.
// act: 0 = relu, 1 = leaky_relu(0.01)
// ===========================================================================
#define LDP 132
static constexpr uint32_t GEMM_SMEM = (2 * 128 * LDP + 128) * 4;  // 135680 B

__global__ __launch_bounds__(512, 1)
void gemm_mma(const float* __restrict__ A1, const float* __restrict__ W1,
              const float* __restrict__ A2, const float* __restrict__ W2,
              const float* __restrict__ bias, void* __restrict__ Cout,
              int N, int act, int half_out)
{
    extern __shared__ uint32_t sm[];
    uint32_t* As = sm;                       // [128][LDP]
    uint32_t* Bs = sm + 128 * LDP;           // [128][LDP]
    float*    bs = (float*)(sm + 2 * 128 * LDP);

    const int tid  = threadIdx.x;
    const int wid  = tid >> 5;
    const int lane = tid & 31;
    const int wm   = (wid & 3) * 32;
    const int wn   = (wid >> 2) * 32;
    const int lr   = lane >> 2;
    const int lc   = lane & 3;
    const int m0   = blockIdx.x * 128;

    if (tid < 128) bs[tid] = bias[tid];

    float acc[2][4][4];
    #pragma unroll
    for (int mi = 0; mi < 2; mi++)
        #pragma unroll
        for (int ni = 0; ni < 4; ni++)
            #pragma unroll
            for (int j = 0; j < 4; j++) acc[mi][ni][j] = 0.f;

    const int npass = (A2 != nullptr) ? 2 : 1;
    for (int p = 0; p < npass; p++) {
        const float* A = p ? A2 : A1;
        const float* W = p ? W2 : W1;

        if (p) __syncthreads();

        #pragma unroll
        for (int i = 0; i < 8; i++) {
            int i4 = i * 512 + tid;
            int r = i4 >> 5, c = (i4 & 31) << 2;
            float4 v = make_float4(0.f, 0.f, 0.f, 0.f);
            if (m0 + r < N) v = *(const float4*)(A + (size_t)(m0 + r) * D + c);
            *(uint4*)(As + r * LDP + c) = make_uint4(tf32r(v.x), tf32r(v.y), tf32r(v.z), tf32r(v.w));
        }
        #pragma unroll
        for (int i = 0; i < 8; i++) {
            int i4 = i * 512 + tid;
            int r = i4 >> 5, c = (i4 & 31) << 2;
            float4 v = *(const float4*)(W + (size_t)r * D + c);
            *(uint4*)(Bs + r * LDP + c) = make_uint4(tf32r(v.x), tf32r(v.y), tf32r(v.z), tf32r(v.w));
        }
        __syncthreads();

        #pragma unroll
        for (int ks = 0; ks < 16; ks++) {
            const int k0 = ks * 8;
            uint32_t af[2][4];
            #pragma unroll
            for (int mi = 0; mi < 2; mi++) {
                int rb = wm + mi * 16 + lr;
                af[mi][0] = As[rb * LDP + k0 + lc];
                af[mi][1] = As[(rb + 8) * LDP + k0 + lc];
                af[mi][2] = As[rb * LDP + k0 + lc + 4];
                af[mi][3] = As[(rb + 8) * LDP + k0 + lc + 4];
            }
            #pragma unroll
            for (int ni = 0; ni < 4; ni++) {
                int cb = wn + ni * 8 + lr;
                uint32_t b0 = Bs[(k0 + lc) * LDP + cb];
                uint32_t b1 = Bs[(k0 + lc + 4) * LDP + cb];
                mma_tf32(acc[0][ni], af[0], b0, b1);
                mma_tf32(acc[1][ni], af[1], b0, b1);
            }
        }
    }

    // Epilogue: bias + activation + store (fp32 or fp16)
    #pragma unroll
    for (int mi = 0; mi < 2; mi++) {
        const int row0 = m0 + wm + mi * 16 + lr;
        #pragma unroll
        for (int ni = 0; ni < 4; ni++) {
            const int col = wn + ni * 8 + lc * 2;
            const float bb0 = bs[col], bb1 = bs[col + 1];
            float v0 = acc[mi][ni][0] + bb0;
            float v1 = acc[mi][ni][1] + bb1;
            float v2 = acc[mi][ni][2] + bb0;
            float v3 = acc[mi][ni][3] + bb1;
            if (act == 0) {
                v0 = fmaxf(v0, 0.f); v1 = fmaxf(v1, 0.f);
                v2 = fmaxf(v2, 0.f); v3 = fmaxf(v3, 0.f);
            } else {
                v0 = v0 > 0.f ? v0 : 0.01f * v0;  v1 = v1 > 0.f ? v1 : 0.01f * v1;
                v2 = v2 > 0.f ? v2 : 0.01f * v2;  v3 = v3 > 0.f ? v3 : 0.01f * v3;
            }
            if (half_out) {
                __half* C = (__half*)Cout;
                if (row0 < N)
                    *(__half2*)(C + (size_t)row0 * D + col) = __floats2half2_rn(v0, v1);
                if (row0 + 8 < N)
                    *(__half2*)(C + (size_t)(row0 + 8) * D + col) = __floats2half2_rn(v2, v3);
            } else {
                float* C = (float*)Cout;
                if (row0 < N)
                    *(float2*)(C + (size_t)row0 * D + col) = make_float2(v0, v1);
                if (row0 + 8 < N)
                    *(float2*)(C + (size_t)(row0 + 8) * D + col) = make_float2(v2, v3);
            }
        }
    }
}

// ===========================================================================
// CSR build (once per launch): deg histogram -> exclusive scan -> ticket fill.
// ===========================================================================
__global__ void zero_deg(int* __restrict__ deg, int n)
{
    int i = blockIdx.x * blockDim.x + threadIdx.x;
    if (i < n) deg[i] = 0;
}

__global__ void hist_deg(const int* __restrict__ dst, int* __restrict__ deg, int E)
{
    int i = blockIdx.x * blockDim.x + threadIdx.x;
    if (i < E) atomicAdd(&deg[dst[i]], 1);
}

// Single-block cooperative exclusive scan, shuffle-based (1024 threads).
__global__ void scan_deg(const int* __restrict__ deg, int* __restrict__ off,
                         int* __restrict__ cur, int n)
{
    __shared__ int wsum[32];
    __shared__ int carry_s;
    const int tid  = threadIdx.x;
    const int lane = tid & 31;
    const int w    = tid >> 5;
    if (tid == 0) carry_s = 0;
    __syncthreads();

    for (int base = 0; base < n; base += 1024) {
        int v = (base + tid < n) ? deg[base + tid] : 0;
        int x = v;
        #pragma unroll
        for (int o = 1; o < 32; o <<= 1) {
            int t = __shfl_up_sync(0xFFFFFFFFu, x, o);
            if (lane >= o) x += t;
        }
        if (lane == 31) wsum[w] = x;
        __syncthreads();
        if (w == 0) {
            int s = wsum[lane];
            #pragma unroll
            for (int o = 1; o < 32; o <<= 1) {
                int t = __shfl_up_sync(0xFFFFFFFFu, s, o);
                if (lane >= o) s += t;
            }
            wsum[lane] = s;
        }
        __syncthreads();
        int incl = x + (w ? wsum[w - 1] : 0);
        int excl = incl - v + carry_s;
        if (base + tid < n) { off[base + tid] = excl; cur[base + tid] = excl; }
        int total = wsum[31];
        __syncthreads();
        if (tid == 0) carry_s += total;
        __syncthreads();
    }
    if (tid == 0) off[n] = carry_s;
}

__global__ void fill_csr(const int* __restrict__ src, const int* __restrict__ dst,
                         int* __restrict__ cur, int* __restrict__ csr, int E)
{
    int i = blockIdx.x * blockDim.x + threadIdx.x;
    if (i < E) {
        int pos = atomicAdd(&cur[dst[i]], 1);
        csr[pos] = src[i];
    }
}

// ===========================================================================
// Gather-max over CSR (fp16 P): 16 lanes per node, uint4 (8 halves) per lane.
// Halves the load-instruction count vs 32-lane/8B; row = one 256B coalesced
// transaction. __hmax2 is exact; empty segment -> zeros (== reference clamp).
// ===========================================================================
__global__ __launch_bounds__(256)
void gather_max(const __half* __restrict__ P, const int* __restrict__ off,
                const int* __restrict__ csr, float* __restrict__ agg, int N)
{
    int gt   = blockIdx.x * blockDim.x + threadIdx.x;
    int node = gt >> 4;          // 16 lanes per node (2 nodes per warp)
    int lane = gt & 15;          // 0..15, owns halves [lane*8, lane*8+8)
    if (node >= N) return;

    int e  = off[node];
    int e1 = off[node + 1];
    const __half2 z = __half2half2(__float2half(0.f));
    __half2 m0 = z, m1 = z, m2 = z, m3 = z;

    const size_t lo = (size_t)lane * 8;

    for (; e + 3 < e1; e += 4) {   // 4-way MLP
        int s0 = csr[e], s1 = csr[e + 1], s2 = csr[e + 2], s3 = csr[e + 3];
        uint4 u0 = *(const uint4*)(P + (size_t)s0 * D + lo);
        uint4 u1 = *(const uint4*)(P + (size_t)s1 * D + lo);
        uint4 u2 = *(const uint4*)(P + (size_t)s2 * D + lo);
        uint4 u3 = *(const uint4*)(P + (size_t)s3 * D + lo);
        m0 = __hmax2(m0, __hmax2(__hmax2(*(__half2*)&u0.x, *(__half2*)&u1.x),
                                 __hmax2(*(__half2*)&u2.x, *(__half2*)&u3.x)));
        m1 = __hmax2(m1, __hmax2(__hmax2(*(__half2*)&u0.y, *(__half2*)&u1.y),
                                 __hmax2(*(__half2*)&u2.y, *(__half2*)&u3.y)));
        m2 = __hmax2(m2, __hmax2(__hmax2(*(__half2*)&u0.z, *(__half2*)&u1.z),
                                 __hmax2(*(__half2*)&u2.z, *(__half2*)&u3.z)));
        m3 = __hmax2(m3, __hmax2(__hmax2(*(__half2*)&u0.w, *(__half2*)&u1.w),
                                 __hmax2(*(__half2*)&u2.w, *(__half2*)&u3.w)));
    }
    for (; e < e1; e++) {
        int s = csr[e];
        uint4 u = *(const uint4*)(P + (size_t)s * D + lo);
        m0 = __hmax2(m0, *(__half2*)&u.x);
        m1 = __hmax2(m1, *(__half2*)&u.y);
        m2 = __hmax2(m2, *(__half2*)&u.z);
        m3 = __hmax2(m3, *(__half2*)&u.w);
    }
    float2 f0 = __half22float2(m0);
    float2 f1 = __half22float2(m1);
    float2 f2 = __half22float2(m2);
    float2 f3 = __half22float2(m3);
    float* ap = agg + (size_t)node * D + lo;
    *(float4*)(ap)     = make_float4(f0.x, f0.y, f1.x, f1.y);
    *(float4*)(ap + 4) = make_float4(f2.x, f2.y, f3.x, f3.y);
}

// ---------------------------------------------------------------------------
// out = sigmoid(h @ Wout + bout), Wout: [128,10]. One warp per node.
// ---------------------------------------------------------------------------
__global__ void out_proj(const float* __restrict__ h, const float* __restrict__ Wout,
                         const float* __restrict__ bout, float* __restrict__ out, int N)
{
    __shared__ float Ws[D * 10];
    __shared__ float bs[10];
    for (int i = threadIdx.x; i < D * 10; i += blockDim.x) Ws[i] = Wout[i];
    if (threadIdx.x < 10) bs[threadIdx.x] = bout[threadIdx.x];
    __syncthreads();

    int gt   = blockIdx.x * blockDim.x + threadIdx.x;
    int node = gt >> 5;
    int lane = gt & 31;
    if (node >= N) return;

    float4 hv = *(const float4*)(h + (size_t)node * D + lane * 4);
#pragma unroll
    for (int c = 0; c < 10; c++) {
        float s = hv.x * Ws[(lane * 4 + 0) * 10 + c]
                + hv.y * Ws[(lane * 4 + 1) * 10 + c]
                + hv.z * Ws[(lane * 4 + 2) * 10 + c]
                + hv.w * Ws[(lane * 4 + 3) * 10 + c];
#pragma unroll
        for (int off = 16; off; off >>= 1) s += __shfl_xor_sync(0xFFFFFFFFu, s, off);
        if (lane == 0) out[(size_t)node * 10 + c] = 1.f / (1.f + expf(-(s + bs[c])));
    }
}

// ---------------------------------------------------------------------------
extern "C" void kernel_launch(void* const* d_in, const int* in_sizes, int n_in,
                              void* d_out, int out_size)
{
    const float* x   = (const float*)d_in[0];
    const int*   src = (const int*)d_in[1];
    const int*   dst = (const int*)d_in[2];
    const float* Wp[3] = {(const float*)d_in[3],  (const float*)d_in[8],  (const float*)d_in[13]};
    const float* bp[3] = {(const float*)d_in[4],  (const float*)d_in[9],  (const float*)d_in[14]};
    const float* Ws[3] = {(const float*)d_in[5],  (const float*)d_in[10], (const float*)d_in[15]};
    const float* Wn[3] = {(const float*)d_in[6],  (const float*)d_in[11], (const float*)d_in[16]};
    const float* bn[3] = {(const float*)d_in[7],  (const float*)d_in[12], (const float*)d_in[17]};
    const float* Wout  = (const float*)d_in[18];
    const float* bout  = (const float*)d_in[19];

    const int N = in_sizes[0] / D;
    const int E = in_sizes[1];

    __half* P;
    float *agg, *h0, *h1;
    int *deg, *off, *cur, *csr;
    cudaGetSymbolAddress((void**)&P,   g_P);
    cudaGetSymbolAddress((void**)&agg, g_agg);
    cudaGetSymbolAddress((void**)&h0,  g_h0);
    cudaGetSymbolAddress((void**)&h1,  g_h1);
    cudaGetSymbolAddress((void**)&deg, g_deg);
    cudaGetSymbolAddress((void**)&off, g_off);
    cudaGetSymbolAddress((void**)&cur, g_cur);
    cudaGetSymbolAddress((void**)&csr, g_csr);

    cudaFuncSetAttribute(gemm_mma, cudaFuncAttributeMaxDynamicSharedMemorySize, GEMM_SMEM);

    // ---- CSR build (dst-grouped incoming edge lists) ----
    zero_deg<<<(N + 255) / 256, 256>>>(deg, N);
    hist_deg<<<(E + 255) / 256, 256>>>(dst, deg, E);
    scan_deg<<<1, 1024>>>(deg, off, cur, N);
    fill_csr<<<(E + 255) / 256, 256>>>(src, dst, cur, csr, E);

    const int gemmBlocks   = (N + 127) / 128;
    const int gatherBlocks = (N * 16 + 255) / 256;

    const float* h = x;
    float* hbuf[3] = {h0, h1, h0};

    for (int l = 0; l < 3; l++) {
        // P = relu(h @ Wpool + bpool), fp16   (gather commutes with linear)
        gemm_mma<<<gemmBlocks, 512, GEMM_SMEM>>>(h, Wp[l], nullptr, nullptr, bp[l], P, N, 0, 1);
        // agg = max over incoming edges of P[src], clamped at 0 (gather, no atomics)
        gather_max<<<gatherBlocks, 256>>>(P, off, csr, agg, N);
        // h' = leaky_relu(h @ Wself + agg @ Wneigh + bneigh)
        gemm_mma<<<gemmBlocks, 512, GEMM_SMEM>>>(h, Ws[l], agg, Wn[l], bn[l], hbuf[l], N, 1, 0);
        h = hbuf[l];
    }

    out_proj<<<(N + 7) / 8, 256>>>(h, Wout, bout, (float*)d_out, N);
}

// round 10
// speedup vs baseline: 3.7333x; 1.1127x over previous
#include <cuda_runtime.h>
#include <cuda_fp16.h>
#include <cstdint>
#include <math.h>

#define NN 50000
#define EE 800000
#define D  128

// Scratch (static __device__ globals: allocation-free per harness rules)
__device__ __half g_P  [NN * D];           // pool output, fp16
__device__ __half g_agg[NN * D];           // gathered max, fp16
__device__ __half g_h0 [NN * D];           // hidden states, fp16
__device__ __half g_h1 [NN * D];
__device__ __half g_Wt [9 * 128 * 136];    // W^T fp16, padded rows (136 halves)
__device__ int    g_deg[NN];
__device__ int    g_off[NN + 1];
__device__ int    g_cur[NN];
__device__ int    g_csr[EE];

// fp16 mma: D(16x8,f32) += A(16x16,f16,row) * B(16x8,f16,col)
__device__ __forceinline__ void mma_f16(float* c, const uint32_t* a, uint32_t b0, uint32_t b1) {
    asm volatile(
        "mma.sync.aligned.m16n8k16.row.col.f32.f16.f16.f32 "
        "{%0,%1,%2,%3}, {%4,%5,%6,%7}, {%8,%9}, {%0,%1,%2,%3};"
        : "+f"(c[0]), "+f"(c[1]), "+f"(c[2]), "+f"(c[3])
        : "r"(a[0]), "r"(a[1]), "r"(a[2]), "r"(a[3]), "r"(b0), "r"(b1));
}

// ===========================================================================
// prep_w: W[k][n] fp32 row-major -> g_Wt[w][n*136 + k] fp16 (transposed,
// padded to 136 halves/row for conflict-free B-fragment loads). Once/launch.
// ===========================================================================
struct WPtrs { const float* p[9]; };

__global__ void prep_w(WPtrs wp)
{
    int w = blockIdx.y;
    int i = blockIdx.x * blockDim.x + threadIdx.x;   // 0..16383
    int k = i >> 7, n = i & 127;
    g_Wt[w * (128 * 136) + n * 136 + k] = __float2half(wp.p[w][i]);
}

// ===========================================================================
// fp16 tensor-core GEMM:  C = act( A1@W1 [+ A2@W2] + bias ),  M128/CTA, N=K=128.
// 512 threads, 16 warps (4m x 4n), warp tile 32x32, 8 k-steps of 16.
// SMEM rows = 68 words (136 halves): frag loads bank-conflict-free.
// A1: fp32 (a1_half=0) or fp16; A2 (optional): fp16. Wt: pre-transposed fp16.
// act: 0=relu, 1=leaky_relu(0.01). half_out: store fp16 vs fp32.
// ===========================================================================
#define LDW 68   // words per SMEM row
static constexpr uint32_t GEMM_SMEM = (2 * 128 * LDW + 128) * 4;  // 70144 B

__global__ __launch_bounds__(512, 1)
void gemm_mma(const void* __restrict__ A1, int a1_half, const __half* __restrict__ W1t,
              const __half* __restrict__ A2h, const __half* __restrict__ W2t,
              const float* __restrict__ bias, void* __restrict__ Cout,
              int N, int act, int half_out)
{
    extern __shared__ uint32_t sm[];
    uint32_t* As = sm;                    // [128][LDW] words (fp16 pairs)
    uint32_t* Bs = sm + 128 * LDW;        // [128][LDW] words
    float*    bs = (float*)(sm + 2 * 128 * LDW);

    const int tid  = threadIdx.x;
    const int wid  = tid >> 5;
    const int lane = tid & 31;
    const int wm   = (wid & 3) * 32;      // warp row offset
    const int wn   = (wid >> 2) * 32;     // warp col offset
    const int lr   = lane >> 2;           // 0..7
    const int lc   = lane & 3;            // 0..3
    const int m0   = blockIdx.x * 128;

    if (tid < 128) bs[tid] = bias[tid];

    float acc[2][4][4];
    #pragma unroll
    for (int mi = 0; mi < 2; mi++)
        #pragma unroll
        for (int ni = 0; ni < 4; ni++)
            #pragma unroll
            for (int j = 0; j < 4; j++) acc[mi][ni][j] = 0.f;

    const int npass = (A2h != nullptr) ? 2 : 1;
    for (int p = 0; p < npass; p++) {
        if (p) __syncthreads();

        // ---- B tile: straight copy of pre-transposed fp16 W (34816 B) ----
        {
            const uint4* src = (const uint4*)(p ? W2t : W1t);
            uint4* dst = (uint4*)Bs;
            for (int i = tid; i < (128 * LDW) / 4; i += 512) dst[i] = src[i];
        }

        // ---- A tile [128 x 128] fp16 into padded rows ----
        if (p == 1 || a1_half) {
            const uint4* src = (const uint4*)(p ? A2h : (const __half*)A1);
            for (int i = tid; i < 2048; i += 512) {         // 2048 uint4 = 32 KB
                int r = i >> 4, q = i & 15;
                uint4 v = make_uint4(0u, 0u, 0u, 0u);
                if (m0 + r < N) v = src[(size_t)(m0 + r) * 16 + q];
                *(uint4*)(As + r * LDW + q * 4) = v;
            }
        } else {
            const float* src = (const float*)A1;
            for (int i = tid; i < 2048; i += 512) {
                int r = i >> 4, q = i & 15;
                uint4 o = make_uint4(0u, 0u, 0u, 0u);
                if (m0 + r < N) {
                    const float4 v0 = *(const float4*)(src + (size_t)(m0 + r) * D + q * 8);
                    const float4 v1 = *(const float4*)(src + (size_t)(m0 + r) * D + q * 8 + 4);
                    *(__half2*)&o.x = __floats2half2_rn(v0.x, v0.y);
                    *(__half2*)&o.y = __floats2half2_rn(v0.z, v0.w);
                    *(__half2*)&o.z = __floats2half2_rn(v1.x, v1.y);
                    *(__half2*)&o.w = __floats2half2_rn(v1.z, v1.w);
                }
                *(uint4*)(As + r * LDW + q * 4) = o;
            }
        }
        __syncthreads();

        // ---- 8 k-steps of m16n8k16 ----
        #pragma unroll
        for (int ks = 0; ks < 8; ks++) {
            const int kw = ks * 8;   // word offset (16 halves)
            uint32_t af[2][4];
            #pragma unroll
            for (int mi = 0; mi < 2; mi++) {
                int rb = wm + mi * 16 + lr;
                af[mi][0] = As[rb * LDW + kw + lc];
                af[mi][1] = As[(rb + 8) * LDW + kw + lc];
                af[mi][2] = As[rb * LDW + kw + 4 + lc];
                af[mi][3] = As[(rb + 8) * LDW + kw + 4 + lc];
            }
            #pragma unroll
            for (int ni = 0; ni < 4; ni++) {
                int cb = wn + ni * 8 + lr;
                uint32_t b0 = Bs[cb * LDW + kw + lc];
                uint32_t b1 = Bs[cb * LDW + kw + 4 + lc];
                mma_f16(acc[0][ni], af[0], b0, b1);
                mma_f16(acc[1][ni], af[1], b0, b1);
            }
        }
    }

    // ---- Epilogue: bias + activation + store ----
    #pragma unroll
    for (int mi = 0; mi < 2; mi++) {
        const int row0 = m0 + wm + mi * 16 + lr;
        #pragma unroll
        for (int ni = 0; ni < 4; ni++) {
            const int col = wn + ni * 8 + lc * 2;
            const float bb0 = bs[col], bb1 = bs[col + 1];
            float v0 = acc[mi][ni][0] + bb0;
            float v1 = acc[mi][ni][1] + bb1;
            float v2 = acc[mi][ni][2] + bb0;
            float v3 = acc[mi][ni][3] + bb1;
            if (act == 0) {
                v0 = fmaxf(v0, 0.f); v1 = fmaxf(v1, 0.f);
                v2 = fmaxf(v2, 0.f); v3 = fmaxf(v3, 0.f);
            } else {
                v0 = v0 > 0.f ? v0 : 0.01f * v0;  v1 = v1 > 0.f ? v1 : 0.01f * v1;
                v2 = v2 > 0.f ? v2 : 0.01f * v2;  v3 = v3 > 0.f ? v3 : 0.01f * v3;
            }
            if (half_out) {
                __half* C = (__half*)Cout;
                if (row0 < N)
                    *(__half2*)(C + (size_t)row0 * D + col) = __floats2half2_rn(v0, v1);
                if (row0 + 8 < N)
                    *(__half2*)(C + (size_t)(row0 + 8) * D + col) = __floats2half2_rn(v2, v3);
            } else {
                float* C = (float*)Cout;
                if (row0 < N)
                    *(float2*)(C + (size_t)row0 * D + col) = make_float2(v0, v1);
                if (row0 + 8 < N)
                    *(float2*)(C + (size_t)(row0 + 8) * D + col) = make_float2(v2, v3);
            }
        }
    }
}

// ===========================================================================
// CSR build (once per launch): deg histogram -> exclusive scan -> ticket fill.
// ===========================================================================
__global__ void zero_deg(int* __restrict__ deg, int n)
{
    int i = blockIdx.x * blockDim.x + threadIdx.x;
    if (i < n) deg[i] = 0;
}

__global__ void hist_deg(const int* __restrict__ dst, int* __restrict__ deg, int E)
{
    int i = blockIdx.x * blockDim.x + threadIdx.x;
    if (i < E) atomicAdd(&deg[dst[i]], 1);
}

// Single-block cooperative exclusive scan, shuffle-based (1024 threads).
__global__ void scan_deg(const int* __restrict__ deg, int* __restrict__ off,
                         int* __restrict__ cur, int n)
{
    __shared__ int wsum[32];
    __shared__ int carry_s;
    const int tid  = threadIdx.x;
    const int lane = tid & 31;
    const int w    = tid >> 5;
    if (tid == 0) carry_s = 0;
    __syncthreads();

    for (int base = 0; base < n; base += 1024) {
        int v = (base + tid < n) ? deg[base + tid] : 0;
        int x = v;
        #pragma unroll
        for (int o = 1; o < 32; o <<= 1) {
            int t = __shfl_up_sync(0xFFFFFFFFu, x, o);
            if (lane >= o) x += t;
        }
        if (lane == 31) wsum[w] = x;
        __syncthreads();
        if (w == 0) {
            int s = wsum[lane];
            #pragma unroll
            for (int o = 1; o < 32; o <<= 1) {
                int t = __shfl_up_sync(0xFFFFFFFFu, s, o);
                if (lane >= o) s += t;
            }
            wsum[lane] = s;
        }
        __syncthreads();
        int incl = x + (w ? wsum[w - 1] : 0);
        int excl = incl - v + carry_s;
        if (base + tid < n) { off[base + tid] = excl; cur[base + tid] = excl; }
        int total = wsum[31];
        __syncthreads();
        if (tid == 0) carry_s += total;
        __syncthreads();
    }
    if (tid == 0) off[n] = carry_s;
}

__global__ void fill_csr(const int* __restrict__ src, const int* __restrict__ dst,
                         int* __restrict__ cur, int* __restrict__ csr, int E)
{
    int i = blockIdx.x * blockDim.x + threadIdx.x;
    if (i < E) {
        int pos = atomicAdd(&cur[dst[i]], 1);
        csr[pos] = src[i];
    }
}

// ===========================================================================
// Gather-max over CSR (fp16): 16 lanes per node, uint4 (8 halves) per lane.
// __hmax2 exact; empty segment -> zeros (== reference clamp). fp16 out.
// ===========================================================================
__global__ __launch_bounds__(256)
void gather_max(const __half* __restrict__ P, const int* __restrict__ off,
                const int* __restrict__ csr, __half* __restrict__ agg, int N)
{
    int gt   = blockIdx.x * blockDim.x + threadIdx.x;
    int node = gt >> 4;          // 16 lanes per node
    int lane = gt & 15;
    if (node >= N) return;

    int e  = off[node];
    int e1 = off[node + 1];
    const __half2 z = __half2half2(__float2half(0.f));
    __half2 m0 = z, m1 = z, m2 = z, m3 = z;

    const size_t lo = (size_t)lane * 8;

    for (; e + 3 < e1; e += 4) {
        int s0 = csr[e], s1 = csr[e + 1], s2 = csr[e + 2], s3 = csr[e + 3];
        uint4 u0 = *(const uint4*)(P + (size_t)s0 * D + lo);
        uint4 u1 = *(const uint4*)(P + (size_t)s1 * D + lo);
        uint4 u2 = *(const uint4*)(P + (size_t)s2 * D + lo);
        uint4 u3 = *(const uint4*)(P + (size_t)s3 * D + lo);
        m0 = __hmax2(m0, __hmax2(__hmax2(*(__half2*)&u0.x, *(__half2*)&u1.x),
                                 __hmax2(*(__half2*)&u2.x, *(__half2*)&u3.x)));
        m1 = __hmax2(m1, __hmax2(__hmax2(*(__half2*)&u0.y, *(__half2*)&u1.y),
                                 __hmax2(*(__half2*)&u2.y, *(__half2*)&u3.y)));
        m2 = __hmax2(m2, __hmax2(__hmax2(*(__half2*)&u0.z, *(__half2*)&u1.z),
                                 __hmax2(*(__half2*)&u2.z, *(__half2*)&u3.z)));
        m3 = __hmax2(m3, __hmax2(__hmax2(*(__half2*)&u0.w, *(__half2*)&u1.w),
                                 __hmax2(*(__half2*)&u2.w, *(__half2*)&u3.w)));
    }
    for (; e < e1; e++) {
        int s = csr[e];
        uint4 u = *(const uint4*)(P + (size_t)s * D + lo);
        m0 = __hmax2(m0, *(__half2*)&u.x);
        m1 = __hmax2(m1, *(__half2*)&u.y);
        m2 = __hmax2(m2, *(__half2*)&u.z);
        m3 = __hmax2(m3, *(__half2*)&u.w);
    }
    uint4 o;
    *(__half2*)&o.x = m0; *(__half2*)&o.y = m1;
    *(__half2*)&o.z = m2; *(__half2*)&o.w = m3;
    *(uint4*)(agg + (size_t)node * D + lo) = o;
}

// ---------------------------------------------------------------------------
// out = sigmoid(h @ Wout + bout), h fp16, Wout: [128,10]. One warp per node.
// ---------------------------------------------------------------------------
__global__ void out_proj(const __half* __restrict__ h, const float* __restrict__ Wout,
                         const float* __restrict__ bout, float* __restrict__ out, int N)
{
    __shared__ float Ws[D * 10];
    __shared__ float bs[10];
    for (int i = threadIdx.x; i < D * 10; i += blockDim.x) Ws[i] = Wout[i];
    if (threadIdx.x < 10) bs[threadIdx.x] = bout[threadIdx.x];
    __syncthreads();

    int gt   = blockIdx.x * blockDim.x + threadIdx.x;
    int node = gt >> 5;
    int lane = gt & 31;
    if (node >= N) return;

    uint2 u = *(const uint2*)(h + (size_t)node * D + lane * 4);
    float2 f0 = __half22float2(*(__half2*)&u.x);
    float2 f1 = __half22float2(*(__half2*)&u.y);
#pragma unroll
    for (int c = 0; c < 10; c++) {
        float s = f0.x * Ws[(lane * 4 + 0) * 10 + c]
                + f0.y * Ws[(lane * 4 + 1) * 10 + c]
                + f1.x * Ws[(lane * 4 + 2) * 10 + c]
                + f1.y * Ws[(lane * 4 + 3) * 10 + c];
#pragma unroll
        for (int off = 16; off; off >>= 1) s += __shfl_xor_sync(0xFFFFFFFFu, s, off);
        if (lane == 0) out[(size_t)node * 10 + c] = 1.f / (1.f + expf(-(s + bs[c])));
    }
}

// ---------------------------------------------------------------------------
extern "C" void kernel_launch(void* const* d_in, const int* in_sizes, int n_in,
                              void* d_out, int out_size)
{
    const float* x   = (const float*)d_in[0];
    const int*   src = (const int*)d_in[1];
    const int*   dst = (const int*)d_in[2];
    const float* Wp[3] = {(const float*)d_in[3],  (const float*)d_in[8],  (const float*)d_in[13]};
    const float* bp[3] = {(const float*)d_in[4],  (const float*)d_in[9],  (const float*)d_in[14]};
    const float* Ws[3] = {(const float*)d_in[5],  (const float*)d_in[10], (const float*)d_in[15]};
    const float* Wn[3] = {(const float*)d_in[6],  (const float*)d_in[11], (const float*)d_in[16]};
    const float* bn[3] = {(const float*)d_in[7],  (const float*)d_in[12], (const float*)d_in[17]};
    const float* Wout  = (const float*)d_in[18];
    const float* bout  = (const float*)d_in[19];

    const int N = in_sizes[0] / D;
    const int E = in_sizes[1];

    __half *P, *agg, *h0, *h1, *Wt;
    int *deg, *off, *cur, *csr;
    cudaGetSymbolAddress((void**)&P,   g_P);
    cudaGetSymbolAddress((void**)&agg, g_agg);
    cudaGetSymbolAddress((void**)&h0,  g_h0);
    cudaGetSymbolAddress((void**)&h1,  g_h1);
    cudaGetSymbolAddress((void**)&Wt,  g_Wt);
    cudaGetSymbolAddress((void**)&deg, g_deg);
    cudaGetSymbolAddress((void**)&off, g_off);
    cudaGetSymbolAddress((void**)&cur, g_cur);
    cudaGetSymbolAddress((void**)&csr, g_csr);

    cudaFuncSetAttribute(gemm_mma, cudaFuncAttributeMaxDynamicSharedMemorySize, GEMM_SMEM);

    // ---- W^T fp16 tiles (once per launch) ----
    WPtrs wp;
    for (int l = 0; l < 3; l++) {
        wp.p[l * 3 + 0] = Wp[l];
        wp.p[l * 3 + 1] = Ws[l];
        wp.p[l * 3 + 2] = Wn[l];
    }
    prep_w<<<dim3(64, 9), 256>>>(wp);

    // ---- CSR build (dst-grouped incoming edge lists) ----
    zero_deg<<<(N + 255) / 256, 256>>>(deg, N);
    hist_deg<<<(E + 255) / 256, 256>>>(dst, deg, E);
    scan_deg<<<1, 1024>>>(deg, off, cur, N);
    fill_csr<<<(E + 255) / 256, 256>>>(src, dst, cur, csr, E);

    const int gemmBlocks   = (N + 127) / 128;
    const int gatherBlocks = (N * 16 + 255) / 256;
    const int WT = 128 * 136;

    const void* h = x;          // layer-0 input is fp32
    int a1h = 0;
    __half* hbuf[3] = {h0, h1, h0};

    for (int l = 0; l < 3; l++) {
        const __half* Wpt = Wt + (size_t)(l * 3 + 0) * WT;
        const __half* Wst = Wt + (size_t)(l * 3 + 1) * WT;
        const __half* Wnt = Wt + (size_t)(l * 3 + 2) * WT;
        // P = relu(h @ Wpool + bpool), fp16   (gather commutes with linear)
        gemm_mma<<<gemmBlocks, 512, GEMM_SMEM>>>(h, a1h, Wpt, nullptr, nullptr, bp[l], P, N, 0, 1);
        // agg = max over incoming edges of P[src], clamped at 0 (no atomics)
        gather_max<<<gatherBlocks, 256>>>(P, off, csr, agg, N);
        // h' = leaky_relu(h @ Wself + agg @ Wneigh + bneigh), fp16
        gemm_mma<<<gemmBlocks, 512, GEMM_SMEM>>>(h, a1h, Wst, agg, Wnt, bn[l], hbuf[l], N, 1, 1);
        h = hbuf[l];
        a1h = 1;
    }

    out_proj<<<(N + 7) / 8, 256>>>((const __half*)h, Wout, bout, (float*)d_out, N);
}